// round 6
// baseline (speedup 1.0000x reference)
#include <cuda_runtime.h>
#include <cstdint>
#include <math.h>

// Problem constants
#define BH 64
#define NSEQ 4096
#define DHEAD 64
#define MFEAT 256
#define DN 0.3535533905932738f   // 64^-0.25
#define HALF_DN2 0.0625f          // 0.5 * 64^-0.5
#define RATIO 0.0625f             // 256^-0.5
#define KEPS 1e-4f
#define CH 16                     // chunks over NSEQ for fused k12
#define STAGES 8                  // (NSEQ/CH)/32 = 256/32

typedef unsigned long long u64;

// Packed fp32x2 helpers (sm_103a FFMA2 path)
__device__ __forceinline__ u64 ffma2(u64 a, u64 b, u64 c) {
    u64 d;
    asm("fma.rn.f32x2 %0, %1, %2, %3;" : "=l"(d) : "l"(a), "l"(b), "l"(c));
    return d;
}
__device__ __forceinline__ u64 fmul2(u64 a, u64 b) {
    u64 d;
    asm("mul.rn.f32x2 %0, %1, %2;" : "=l"(d) : "l"(a), "l"(b));
    return d;
}
__device__ __forceinline__ u64 pack2(float lo, float hi) {
    u64 d; asm("mov.b64 %0, {%1, %2};" : "=l"(d) : "f"(lo), "f"(hi)); return d;
}
__device__ __forceinline__ float2 unpack2(u64 v) {
    float lo, hi; asm("mov.b64 {%0, %1}, %2;" : "=f"(lo), "=f"(hi) : "l"(v));
    return make_float2(lo, hi);
}

// cp.async helpers
__device__ __forceinline__ void cp_async16(uint32_t s, const void* g) {
    asm volatile("cp.async.cg.shared.global [%0], [%1], 16;" :: "r"(s), "l"(g));
}
__device__ __forceinline__ void cp_commit() {
    asm volatile("cp.async.commit_group;" ::: "memory");
}
__device__ __forceinline__ void cp_wait0() {
    asm volatile("cp.async.wait_group 0;" ::: "memory");
}

// Scratch (device globals: allocation-free). All entries fully rewritten each call.
__device__ float g_ctx_part[(size_t)BH * CH * MFEAT * DHEAD]; // 67 MB
__device__ float g_ksum_part[BH * CH * MFEAT];
__device__ float g_lmax[BH * CH];
__device__ float g_scale[BH * CH];
__device__ float g_vsum[BH * DHEAD];
__device__ float g_ctx[(size_t)BH * MFEAT * DHEAD];           // 4 MB
__device__ float g_ksum[BH * MFEAT];

// ---------------------------------------------------------------------------
// Fused kernel: K features + partial context/ksum with running-max rescaling.
// Grid (CH, BH), 256 threads. Thread j owns feature j. cp.async double buffer.
// ---------------------------------------------------------------------------
__global__ __launch_bounds__(256, 1) void k12_ctx(const float* __restrict__ K,
                                                  const float* __restrict__ V,
                                                  const float* __restrict__ P) {
    __shared__ __align__(16) float ksm[2][32 * 64];  // 16KB
    __shared__ __align__(16) float vsm[2][32 * 64];  // 16KB
    __shared__ float diag[32];
    __shared__ float wmax[8];
    const int bh = blockIdx.y, chunk = blockIdx.x, t = threadIdx.x;
    const int w = t >> 5, lane = t & 31;

    u64 p2[32];
    {
        const ulonglong2* pr = (const ulonglong2*)(P + t * 64);
        #pragma unroll
        for (int i = 0; i < 16; i++) { ulonglong2 x = pr[i]; p2[2*i] = x.x; p2[2*i+1] = x.y; }
    }

    const float4* kb = (const float4*)K + ((size_t)bh * NSEQ + (size_t)chunk * 256) * 16;
    const float4* vb = (const float4*)V + ((size_t)bh * NSEQ + (size_t)chunk * 256) * 16;

    uint32_t ks_s0 = (uint32_t)__cvta_generic_to_shared(ksm[0]);
    uint32_t ks_s1 = (uint32_t)__cvta_generic_to_shared(ksm[1]);
    uint32_t vs_s0 = (uint32_t)__cvta_generic_to_shared(vsm[0]);
    uint32_t vs_s1 = (uint32_t)__cvta_generic_to_shared(vsm[1]);

    // Prologue: stage 0 into buffer 0.
    cp_async16(ks_s0 + t * 16, kb + t);
    cp_async16(ks_s0 + (t + 256) * 16, kb + t + 256);
    cp_async16(vs_s0 + t * 16, vb + t);
    cp_async16(vs_s0 + (t + 256) * 16, vb + t + 256);
    cp_commit();

    u64 ctx2[32];
    #pragma unroll
    for (int i = 0; i < 32; i++) ctx2[i] = 0ull;
    float ks = 0.f, M = -1e30f;

    for (int st = 0; st < STAGES; st++) {
        const int buf = st & 1;
        cp_wait0();
        __syncthreads();   // stage data visible to all; previous compute done

        if (st + 1 < STAGES) {
            const float4* kn = kb + (st + 1) * 512;
            const float4* vn = vb + (st + 1) * 512;
            uint32_t kd = (buf ? ks_s0 : ks_s1);
            uint32_t vd = (buf ? vs_s0 : vs_s1);
            cp_async16(kd + t * 16, kn + t);
            cp_async16(kd + (t + 256) * 16, kn + t + 256);
            cp_async16(vd + t * 16, vn + t);
            cp_async16(vd + (t + 256) * 16, vn + t + 256);
            cp_commit();
        }

        const float* ksb = ksm[buf];
        const float* vsb = vsm[buf];

        // diag: 8 threads per row sum-of-squares
        {
            int r = t >> 3, seg = t & 7;
            const float4* kr = (const float4*)(ksb + r * 64) + seg * 2;
            float4 a = kr[0], b = kr[1];
            float ss = a.x*a.x + a.y*a.y + a.z*a.z + a.w*a.w
                     + b.x*b.x + b.y*b.y + b.z*b.z + b.w*b.w;
            ss += __shfl_xor_sync(0xffffffffu, ss, 1);
            ss += __shfl_xor_sync(0xffffffffu, ss, 2);
            ss += __shfl_xor_sync(0xffffffffu, ss, 4);
            if (seg == 0) diag[r] = HALF_DN2 * ss;
        }

        // dd for 32 rows into registers; track thread max.
        float dd_r[32];
        float mj = -1e30f;
        #pragma unroll 2
        for (int r = 0; r < 32; r++) {
            const ulonglong2* krow = (const ulonglong2*)(ksb + r * 64);
            u64 a0 = 0, a1 = 0, a2 = 0, a3 = 0;
            #pragma unroll
            for (int i = 0; i < 8; i++) {
                ulonglong2 ka = krow[2*i];
                ulonglong2 kc = krow[2*i+1];
                a0 = ffma2(ka.x, p2[4*i],   a0);
                a1 = ffma2(ka.y, p2[4*i+1], a1);
                a2 = ffma2(kc.x, p2[4*i+2], a2);
                a3 = ffma2(kc.y, p2[4*i+3], a3);
            }
            float2 f0 = unpack2(a0), f1 = unpack2(a1);
            float2 f2 = unpack2(a2), f3 = unpack2(a3);
            float s = ((f0.x + f0.y) + (f1.x + f1.y)) + ((f2.x + f2.y) + (f3.x + f3.y));
            dd_r[r] = DN * s;
            mj = fmaxf(mj, dd_r[r]);
        }
        #pragma unroll
        for (int o = 16; o; o >>= 1) mj = fmaxf(mj, __shfl_xor_sync(0xffffffffu, mj, o));
        if (lane == 0) wmax[w] = mj;
        __syncthreads();   // wmax + diag visible

        float smax = wmax[0];
        #pragma unroll
        for (int i = 1; i < 8; i++) smax = fmaxf(smax, wmax[i]);
        if (smax > M) {    // same decision in every thread (CTA-uniform smax)
            float sc = __expf(M - smax);
            u64 sc2 = pack2(sc, sc);
            #pragma unroll
            for (int i = 0; i < 32; i++) ctx2[i] = fmul2(ctx2[i], sc2);
            ks *= sc;
            M = smax;
        }

        // exp + ctx accumulation.
        #pragma unroll 2
        for (int r = 0; r < 32; r++) {
            float kp = __expf(dd_r[r] - diag[r] - M);
            ks += kp;
            u64 kp2 = pack2(kp, kp);
            const ulonglong2* vrow = (const ulonglong2*)(vsb + r * 64);
            #pragma unroll
            for (int i = 0; i < 16; i++) {
                ulonglong2 vv = vrow[i];
                ctx2[2*i]   = ffma2(kp2, vv.x, ctx2[2*i]);
                ctx2[2*i+1] = ffma2(kp2, vv.y, ctx2[2*i+1]);
            }
        }
    }

    ulonglong2* outp = (ulonglong2*)(g_ctx_part +
        (((size_t)bh * CH + chunk) * MFEAT + t) * DHEAD);
    #pragma unroll
    for (int i = 0; i < 16; i++)
        outp[i] = make_ulonglong2(ctx2[2*i], ctx2[2*i+1]);
    g_ksum_part[(bh * CH + chunk) * MFEAT + t] = ks;
    if (t == 0) g_lmax[bh * CH + chunk] = M;
}

// ---------------------------------------------------------------------------
// vsum[bh][e] = sum_n V[bh][n][e]  (for the analytic eps term)
// ---------------------------------------------------------------------------
__global__ __launch_bounds__(256) void kvsum(const float* __restrict__ V) {
    __shared__ float psum[16][64];
    const int bh = blockIdx.x, t = threadIdx.x;
    const int e4 = t & 15, rc = t >> 4;
    const float4* vb = (const float4*)V + (size_t)bh * NSEQ * 16;
    float4 acc = make_float4(0.f, 0.f, 0.f, 0.f);
    #pragma unroll 8
    for (int it = 0; it < 256; it++) {
        float4 a = vb[(size_t)(rc + 16 * it) * 16 + e4];
        acc.x += a.x; acc.y += a.y; acc.z += a.z; acc.w += a.w;
    }
    psum[rc][e4*4+0] = acc.x; psum[rc][e4*4+1] = acc.y;
    psum[rc][e4*4+2] = acc.z; psum[rc][e4*4+3] = acc.w;
    __syncthreads();
    if (t < 64) {
        float s = 0.f;
        #pragma unroll
        for (int r = 0; r < 16; r++) s += psum[r][t];
        g_vsum[bh * 64 + t] = s;
    }
}

// ---------------------------------------------------------------------------
// Per-bh global stab + per-chunk scale factors.
// ---------------------------------------------------------------------------
__global__ void kscale() {
    const int bh = threadIdx.x;  // 64 threads
    float mx = -1e30f;
    #pragma unroll
    for (int c = 0; c < CH; c++) mx = fmaxf(mx, g_lmax[bh * CH + c]);
    #pragma unroll
    for (int c = 0; c < CH; c++)
        g_scale[bh * CH + c] = __expf(g_lmax[bh * CH + c] - mx);
}

// ---------------------------------------------------------------------------
// Reduce partials with rescale; add eps terms; apply RATIO.
// ---------------------------------------------------------------------------
__global__ void k2_reduce() {
    const size_t NCTX = (size_t)BH * MFEAT * DHEAD;  // 1048576
    size_t idx = (size_t)blockIdx.x * 256 + threadIdx.x;
    if (idx < NCTX) {
        size_t bh = idx >> 14;
        size_t rem = idx & 16383;
        size_t e = idx & 63;
        float s = 0.f;
        #pragma unroll
        for (int c = 0; c < CH; c++)
            s += g_scale[bh * CH + c] * g_ctx_part[(((size_t)bh * CH + c) << 14) + rem];
        g_ctx[idx] = RATIO * (s + KEPS * g_vsum[(bh << 6) + e]);
    } else if (idx < NCTX + (size_t)BH * MFEAT) {
        size_t i2 = idx - NCTX;
        size_t bh = i2 >> 8, j = i2 & 255;
        float s = 0.f;
        #pragma unroll
        for (int c = 0; c < CH; c++)
            s += g_scale[bh * CH + c] * g_ksum_part[(bh * CH + c) * MFEAT + j];
        g_ksum[i2] = RATIO * (s + KEPS * (float)NSEQ);
    }
}

// ---------------------------------------------------------------------------
// Kernel 3: q-side features + D_inv + output GEMM, 128-row tiles, FFMA2.
// Dynamic smem: dds [128][257] (131584B) + overlay (qsm 32KB then ctx 64KB).
// ---------------------------------------------------------------------------
#define K3_SMEM_BYTES (131584 + 65536)

__global__ __launch_bounds__(256, 1) void k3_out(const float* __restrict__ Q,
                                                 const float* __restrict__ P,
                                                 float* __restrict__ O) {
    extern __shared__ __align__(16) char smraw[];
    float (*dds)[257] = (float (*)[257])smraw;            // [128][257]
    float* ovl  = (float*)(smraw + 131584);               // 64KB overlay
    float (*qsm)[64] = (float (*)[64])ovl;                // phase 1-2: Q tile
    float* ctxs = ovl;                                    // phase 3+: ctx
    __shared__ float ksum_s[256];
    __shared__ float diag[128];
    __shared__ float rmax[128];
    __shared__ float dinv[128];

    const int bh = blockIdx.y, tile = blockIdx.x, t = threadIdx.x;
    const int w = t >> 5, lane = t & 31;

    u64 p2[32];
    {
        const ulonglong2* pr = (const ulonglong2*)(P + t * 64);
        #pragma unroll
        for (int i = 0; i < 16; i++) { ulonglong2 tt = pr[i]; p2[2*i] = tt.x; p2[2*i+1] = tt.y; }
    }
    ksum_s[t] = g_ksum[bh * MFEAT + t];

    // Load Q tile (128 x 64) + per-row diag via 16-lane shuffles.
    {
        const float4* qb = (const float4*)(Q + ((size_t)bh * NSEQ + (size_t)tile * 128) * DHEAD);
        float4* qs = (float4*)&qsm[0][0];
        #pragma unroll
        for (int kq = 0; kq < 8; kq++) {
            int i = t + 256 * kq;          // float4 index; row = i >> 4
            float4 a = qb[i];
            qs[i] = a;
            float ss = a.x*a.x + a.y*a.y + a.z*a.z + a.w*a.w;
            #pragma unroll
            for (int o = 1; o < 16; o <<= 1) ss += __shfl_xor_sync(0xffffffffu, ss, o);
            if ((t & 15) == 0) diag[i >> 4] = HALF_DN2 * ss;
        }
    }
    __syncthreads();

    // dd[r][t] = DN * dot(q[r], proj[t])   (FFMA2)
    #pragma unroll 2
    for (int r = 0; r < 128; r++) {
        const ulonglong2* qrow = (const ulonglong2*)qsm[r];
        u64 acc0 = 0, acc1 = 0, acc2 = 0, acc3 = 0;
        #pragma unroll
        for (int i = 0; i < 8; i++) {
            ulonglong2 qa = qrow[2*i];
            ulonglong2 qb2 = qrow[2*i+1];
            acc0 = ffma2(qa.x,  p2[4*i],   acc0);
            acc1 = ffma2(qa.y,  p2[4*i+1], acc1);
            acc2 = ffma2(qb2.x, p2[4*i+2], acc2);
            acc3 = ffma2(qb2.y, p2[4*i+3], acc3);
        }
        float2 f0 = unpack2(acc0), f1 = unpack2(acc1);
        float2 f2 = unpack2(acc2), f3 = unpack2(acc3);
        float s = ((f0.x + f0.y) + (f1.x + f1.y)) + ((f2.x + f2.y) + (f3.x + f3.y));
        dds[r][t] = DN * s;
    }
    __syncthreads();

    // ctx load into overlay (qsm dead now); overlaps the reduction phases.
    {
        const float4* cg = (const float4*)(g_ctx + (size_t)bh * MFEAT * DHEAD);
        float4* cs = (float4*)ctxs;
        #pragma unroll
        for (int i = 0; i < 16; i++) cs[t + 256 * i] = cg[t + 256 * i];
    }

    // Per-row max (16 rows per warp).
    #pragma unroll
    for (int rr = 0; rr < 16; rr++) {
        int r = w * 16 + rr;
        float m = dds[r][lane];
        #pragma unroll
        for (int c = 1; c < 8; c++) m = fmaxf(m, dds[r][lane + 32 * c]);
        #pragma unroll
        for (int o = 16; o; o >>= 1) m = fmaxf(m, __shfl_xor_sync(0xffffffffu, m, o));
        if (lane == 0) rmax[r] = m;
    }
    __syncthreads();

    // q' = ratio*(exp(dd - diag - rowmax) + eps), in-place
    #pragma unroll 4
    for (int r = 0; r < 128; r++)
        dds[r][t] = RATIO * (__expf(dds[r][t] - diag[r] - rmax[r]) + KEPS);
    __syncthreads();

    // D_inv[r] = 1 / dot(q'[r], ksum)  (16 rows per warp)
    #pragma unroll
    for (int rr = 0; rr < 16; rr++) {
        int r = w * 16 + rr;
        float s = 0.f;
        #pragma unroll
        for (int c = 0; c < 8; c++)
            s = fmaf(dds[r][lane + 32 * c], ksum_s[lane + 32 * c], s);
        #pragma unroll
        for (int o = 16; o; o >>= 1) s += __shfl_xor_sync(0xffffffffu, s, o);
        if (lane == 0) dinv[r] = 1.0f / s;
    }
    __syncthreads();

    // out[r][e]: 4 rows x 8 cols per thread via FFMA2.
    const int rs = t >> 3;           // rows rs, rs+32, rs+64, rs+96
    const int ecg = (t & 7) * 2;     // ulonglong2 index within 64-float row
    const ulonglong2* cc = (const ulonglong2*)ctxs;
    u64 a0[4], a1[4], a2[4], a3[4];
    #pragma unroll
    for (int i = 0; i < 4; i++) { a0[i]=0; a1[i]=0; a2[i]=0; a3[i]=0; }
    #pragma unroll 2
    for (int jj = 0; jj < 256; jj++) {
        ulonglong2 cA = cc[jj * 16 + ecg];
        ulonglong2 cB = cc[jj * 16 + ecg + 1];
        float v0 = dds[rs][jj];
        float v1 = dds[rs + 32][jj];
        float v2 = dds[rs + 64][jj];
        float v3 = dds[rs + 96][jj];
        u64 q0 = pack2(v0, v0), q1 = pack2(v1, v1);
        u64 q2 = pack2(v2, v2), q3 = pack2(v3, v3);
        a0[0] = ffma2(q0, cA.x, a0[0]); a0[1] = ffma2(q0, cA.y, a0[1]);
        a0[2] = ffma2(q0, cB.x, a0[2]); a0[3] = ffma2(q0, cB.y, a0[3]);
        a1[0] = ffma2(q1, cA.x, a1[0]); a1[1] = ffma2(q1, cA.y, a1[1]);
        a1[2] = ffma2(q1, cB.x, a1[2]); a1[3] = ffma2(q1, cB.y, a1[3]);
        a2[0] = ffma2(q2, cA.x, a2[0]); a2[1] = ffma2(q2, cA.y, a2[1]);
        a2[2] = ffma2(q2, cB.x, a2[2]); a2[3] = ffma2(q2, cB.y, a2[3]);
        a3[0] = ffma2(q3, cA.x, a3[0]); a3[1] = ffma2(q3, cA.y, a3[1]);
        a3[2] = ffma2(q3, cB.x, a3[2]); a3[3] = ffma2(q3, cB.y, a3[3]);
    }
    // Column offset in floats = ecg * 4 (one ulonglong2 = 4 floats).
    float* obase = O + ((size_t)bh * NSEQ + (size_t)tile * 128) * DHEAD + (size_t)ecg * 4;
    {
        u64 d2;
        d2 = pack2(dinv[rs], dinv[rs]);
        ((ulonglong2*)(obase + (size_t)rs * 64))[0] = make_ulonglong2(fmul2(a0[0], d2), fmul2(a0[1], d2));
        ((ulonglong2*)(obase + (size_t)rs * 64))[1] = make_ulonglong2(fmul2(a0[2], d2), fmul2(a0[3], d2));
        d2 = pack2(dinv[rs + 32], dinv[rs + 32]);
        ((ulonglong2*)(obase + (size_t)(rs + 32) * 64))[0] = make_ulonglong2(fmul2(a1[0], d2), fmul2(a1[1], d2));
        ((ulonglong2*)(obase + (size_t)(rs + 32) * 64))[1] = make_ulonglong2(fmul2(a1[2], d2), fmul2(a1[3], d2));
        d2 = pack2(dinv[rs + 64], dinv[rs + 64]);
        ((ulonglong2*)(obase + (size_t)(rs + 64) * 64))[0] = make_ulonglong2(fmul2(a2[0], d2), fmul2(a2[1], d2));
        ((ulonglong2*)(obase + (size_t)(rs + 64) * 64))[1] = make_ulonglong2(fmul2(a2[2], d2), fmul2(a2[3], d2));
        d2 = pack2(dinv[rs + 96], dinv[rs + 96]);
        ((ulonglong2*)(obase + (size_t)(rs + 96) * 64))[0] = make_ulonglong2(fmul2(a3[0], d2), fmul2(a3[1], d2));
        ((ulonglong2*)(obase + (size_t)(rs + 96) * 64))[1] = make_ulonglong2(fmul2(a3[2], d2), fmul2(a3[3], d2));
    }
}

// ---------------------------------------------------------------------------
extern "C" void kernel_launch(void* const* d_in, const int* in_sizes, int n_in,
                              void* d_out, int out_size) {
    const float* q    = (const float*)d_in[0];
    const float* k    = (const float*)d_in[1];
    const float* v    = (const float*)d_in[2];
    const float* proj = (const float*)d_in[3];
    float* out = (float*)d_out;

    cudaFuncSetAttribute(k3_out, cudaFuncAttributeMaxDynamicSharedMemorySize,
                         K3_SMEM_BYTES);

    k12_ctx<<<dim3(CH, BH), 256>>>(k, v, proj);
    kvsum<<<BH, 256>>>(v);
    kscale<<<1, BH>>>();
    {
        const size_t total = (size_t)BH * MFEAT * DHEAD + (size_t)BH * MFEAT;
        k2_reduce<<<(unsigned)((total + 255) / 256), 256>>>();
    }
    k3_out<<<dim3(NSEQ / 128, BH), 256, K3_SMEM_BYTES>>>(q, proj, out);
}

// round 8
// speedup vs baseline: 1.0305x; 1.0305x over previous
#include <cuda_runtime.h>
#include <cstdint>
#include <math.h>

// Problem constants
#define BH 64
#define NSEQ 4096
#define DHEAD 64
#define MFEAT 256
#define DN 0.3535533905932738f   // 64^-0.25
#define HALF_DN2 0.0625f          // 0.5 * 64^-0.5
#define RATIO 0.0625f             // 256^-0.5
#define KEPS 1e-4f
#define CH 16                     // row-chunks for k12 (256 rows each)
#define STAGES 8                  // 256/32 rows per stage

typedef unsigned long long u64;

// Packed fp32x2 helpers
__device__ __forceinline__ u64 ffma2(u64 a, u64 b, u64 c) {
    u64 d;
    asm("fma.rn.f32x2 %0, %1, %2, %3;" : "=l"(d) : "l"(a), "l"(b), "l"(c));
    return d;
}
__device__ __forceinline__ u64 fmul2(u64 a, u64 b) {
    u64 d;
    asm("mul.rn.f32x2 %0, %1, %2;" : "=l"(d) : "l"(a), "l"(b));
    return d;
}
__device__ __forceinline__ u64 pack2(float lo, float hi) {
    u64 d; asm("mov.b64 %0, {%1, %2};" : "=l"(d) : "f"(lo), "f"(hi)); return d;
}
__device__ __forceinline__ float2 unpack2(u64 v) {
    float lo, hi; asm("mov.b64 {%0, %1}, %2;" : "=f"(lo), "=f"(hi) : "l"(v));
    return make_float2(lo, hi);
}

// cp.async helpers
__device__ __forceinline__ void cp_async16(uint32_t s, const void* g) {
    asm volatile("cp.async.cg.shared.global [%0], [%1], 16;" :: "r"(s), "l"(g));
}
__device__ __forceinline__ void cp_commit() {
    asm volatile("cp.async.commit_group;" ::: "memory");
}
__device__ __forceinline__ void cp_wait0() {
    asm volatile("cp.async.wait_group 0;" ::: "memory");
}

// Scratch (device globals). All entries fully rewritten each call.
__device__ float g_ctx_part[(size_t)BH * CH * MFEAT * DHEAD]; // 67 MB
__device__ float g_ksum_part[BH * CH * MFEAT];
__device__ float g_lmax[BH * CH * 2];
__device__ float g_scale[BH * CH * 2];
__device__ float g_vsum[BH * DHEAD];
__device__ float g_ctx[(size_t)BH * MFEAT * DHEAD];           // 4 MB
__device__ float g_ksum[BH * MFEAT];

// ---------------------------------------------------------------------------
// k12: fused K-features + partial ctx/ksum, outer-product form, 2 CTAs/SM.
// Grid (CH*2, BH): blockIdx.x = chunk*2 + fh; CTA owns 128 features, 256 rows.
// Dyn smem (bytes): Pt[64][132] @0 (33792) | Ks[2][32][68] @33792 (17408) |
//                   Vs[2][32][64] @51200 (16384) | kps[32][132] @67584 (16896)
// total 84480 -> 2 CTAs/SM.
// ---------------------------------------------------------------------------
#define K12_SMEM 84480

__global__ __launch_bounds__(256, 2) void k12_ctx(const float* __restrict__ K,
                                                  const float* __restrict__ V,
                                                  const float* __restrict__ P) {
    extern __shared__ __align__(16) char smraw[];
    float* Pt  = (float*)smraw;                    // [64][132]
    float* Ks  = (float*)(smraw + 33792);          // [2][32][68]
    float* Vs  = (float*)(smraw + 51200);          // [2][32][64]
    float* kps = (float*)(smraw + 67584);          // [32][132]
    __shared__ float wmax[8];

    const int bh = blockIdx.y;
    const int chunk = blockIdx.x >> 1;
    const int fh = blockIdx.x & 1;
    const int fbase = fh * 128;
    const int t = threadIdx.x;
    const int w = t >> 5, lane = t & 31;

    const float* kb = K + ((size_t)bh * NSEQ + (size_t)chunk * 256) * 64;
    const float* vb = V + ((size_t)bh * NSEQ + (size_t)chunk * 256) * 64;

    uint32_t ks_s = (uint32_t)__cvta_generic_to_shared(Ks);
    uint32_t vs_s = (uint32_t)__cvta_generic_to_shared(Vs);

    // Prologue: stage 0 (buf 0). Each thread: 2 K-chunks + 2 V-chunks of 16B.
    {
        int c0 = t, c1 = t + 256;
        int r0 = c0 >> 4, q0 = c0 & 15, r1 = c1 >> 4, q1 = c1 & 15;
        cp_async16(ks_s + r0 * 272 + q0 * 16, kb + r0 * 64 + q0 * 4);
        cp_async16(ks_s + r1 * 272 + q1 * 16, kb + r1 * 64 + q1 * 4);
        cp_async16(vs_s + r0 * 256 + q0 * 16, vb + r0 * 64 + q0 * 4);
        cp_async16(vs_s + r1 * 256 + q1 * 16, vb + r1 * 64 + q1 * 4);
        cp_commit();
    }

    // Load P slice transposed: Pt[d][f] = P[fbase+f][d], f in [0,128).
    for (int idx = t; idx < 128 * 64; idx += 256) {
        int f = idx >> 6, d = idx & 63;
        Pt[d * 132 + f] = P[(size_t)(fbase + f) * 64 + d];
    }

    u64 ctx2[16];          // [4 features][4 e-pairs] -> f = lane*4+j, e = w*8..+7
    #pragma unroll
    for (int i = 0; i < 16; i++) ctx2[i] = 0ull;
    float ks0 = 0.f, ks1 = 0.f, ks2 = 0.f, ks3 = 0.f;
    float M = -1e30f;

    for (int st = 0; st < STAGES; st++) {
        const int buf = st & 1;
        cp_wait0();
        __syncthreads();

        if (st + 1 < STAGES) {
            const float* kn = kb + (st + 1) * 32 * 64;
            const float* vn = vb + (st + 1) * 32 * 64;
            uint32_t kd = ks_s + (buf ^ 1) * 8704;
            uint32_t vd = vs_s + (buf ^ 1) * 8192;
            int c0 = t, c1 = t + 256;
            int r0 = c0 >> 4, q0 = c0 & 15, r1 = c1 >> 4, q1 = c1 & 15;
            cp_async16(kd + r0 * 272 + q0 * 16, kn + r0 * 64 + q0 * 4);
            cp_async16(kd + r1 * 272 + q1 * 16, kn + r1 * 64 + q1 * 4);
            cp_async16(vd + r0 * 256 + q0 * 16, vn + r0 * 64 + q0 * 4);
            cp_async16(vd + r1 * 256 + q1 * 16, vn + r1 * 64 + q1 * 4);
            cp_commit();
        }

        const float* ksb = Ks + buf * 2176;   // floats
        const float* vsb = Vs + buf * 2048;

        // diag for this warp's 4 rows (register-resident, warp-local rows).
        float diag_r[4];
        #pragma unroll
        for (int i = 0; i < 4; i++) {
            const float* kr = ksb + (w * 4 + i) * 68;
            float2 v2 = *(const float2*)(kr + 2 * lane);
            float ss = v2.x * v2.x + v2.y * v2.y;
            #pragma unroll
            for (int o = 16; o; o >>= 1) ss += __shfl_xor_sync(0xffffffffu, ss, o);
            diag_r[i] = HALF_DN2 * ss;
        }

        // dd outer product: rows w*4..+3  x  features lane*4..+3.
        u64 acc[4][2];
        #pragma unroll
        for (int i = 0; i < 4; i++) { acc[i][0] = 0ull; acc[i][1] = 0ull; }
        const float* kr0 = ksb + (w * 4 + 0) * 68;
        const float* kr1 = ksb + (w * 4 + 1) * 68;
        const float* kr2 = ksb + (w * 4 + 2) * 68;
        const float* kr3 = ksb + (w * 4 + 3) * 68;
        #pragma unroll 4
        for (int d = 0; d < 64; d += 4) {
            float4 k0 = *(const float4*)(kr0 + d);
            float4 k1 = *(const float4*)(kr1 + d);
            float4 k2 = *(const float4*)(kr2 + d);
            float4 k3 = *(const float4*)(kr3 + d);
            #pragma unroll
            for (int q = 0; q < 4; q++) {
                ulonglong2 pv = *(const ulonglong2*)(Pt + (d + q) * 132 + lane * 4);
                float kq0 = (q == 0) ? k0.x : (q == 1) ? k0.y : (q == 2) ? k0.z : k0.w;
                float kq1 = (q == 0) ? k1.x : (q == 1) ? k1.y : (q == 2) ? k1.z : k1.w;
                float kq2 = (q == 0) ? k2.x : (q == 1) ? k2.y : (q == 2) ? k2.z : k2.w;
                float kq3 = (q == 0) ? k3.x : (q == 1) ? k3.y : (q == 2) ? k3.z : k3.w;
                u64 b0 = pack2(kq0, kq0), b1 = pack2(kq1, kq1);
                u64 b2 = pack2(kq2, kq2), b3 = pack2(kq3, kq3);
                acc[0][0] = ffma2(b0, pv.x, acc[0][0]); acc[0][1] = ffma2(b0, pv.y, acc[0][1]);
                acc[1][0] = ffma2(b1, pv.x, acc[1][0]); acc[1][1] = ffma2(b1, pv.y, acc[1][1]);
                acc[2][0] = ffma2(b2, pv.x, acc[2][0]); acc[2][1] = ffma2(b2, pv.y, acc[2][1]);
                acc[3][0] = ffma2(b3, pv.x, acc[3][0]); acc[3][1] = ffma2(b3, pv.y, acc[3][1]);
            }
        }

        // dd values, local max.
        float dd[4][4];
        float mx = -1e30f;
        #pragma unroll
        for (int i = 0; i < 4; i++) {
            float2 lo = unpack2(acc[i][0]);
            float2 hi = unpack2(acc[i][1]);
            dd[i][0] = DN * lo.x; dd[i][1] = DN * lo.y;
            dd[i][2] = DN * hi.x; dd[i][3] = DN * hi.y;
            mx = fmaxf(mx, fmaxf(fmaxf(dd[i][0], dd[i][1]), fmaxf(dd[i][2], dd[i][3])));
        }
        #pragma unroll
        for (int o = 16; o; o >>= 1) mx = fmaxf(mx, __shfl_xor_sync(0xffffffffu, mx, o));
        if (lane == 0) wmax[w] = mx;
        __syncthreads();
        float smax = wmax[0];
        #pragma unroll
        for (int i = 1; i < 8; i++) smax = fmaxf(smax, wmax[i]);

        if (smax > M) {   // CTA-uniform
            float sc = __expf(M - smax);
            u64 sc2 = pack2(sc, sc);
            #pragma unroll
            for (int i = 0; i < 16; i++) ctx2[i] = fmul2(ctx2[i], sc2);
            ks0 *= sc; ks1 *= sc; ks2 *= sc; ks3 *= sc;
            M = smax;
        }

        // exp in regs, accumulate ksum, store kp tile to shared.
        #pragma unroll
        for (int i = 0; i < 4; i++) {
            float k0 = __expf(dd[i][0] - diag_r[i] - M);
            float k1 = __expf(dd[i][1] - diag_r[i] - M);
            float k2 = __expf(dd[i][2] - diag_r[i] - M);
            float k3 = __expf(dd[i][3] - diag_r[i] - M);
            ks0 += k0; ks1 += k1; ks2 += k2; ks3 += k3;
            *(float4*)(kps + (w * 4 + i) * 132 + lane * 4) = make_float4(k0, k1, k2, k3);
        }
        __syncthreads();

        // ctx outer product: features lane*4..+3  x  e-cols w*8..+7.
        #pragma unroll 4
        for (int r = 0; r < 32; r++) {
            ulonglong2 kp4 = *(const ulonglong2*)(kps + r * 132 + lane * 4);
            float2 klo = unpack2(kp4.x), khi = unpack2(kp4.y);
            u64 b0 = pack2(klo.x, klo.x), b1 = pack2(klo.y, klo.y);
            u64 b2 = pack2(khi.x, khi.x), b3 = pack2(khi.y, khi.y);
            const ulonglong2* vp = (const ulonglong2*)(vsb + r * 64 + w * 8);
            ulonglong2 vA = vp[0], vB = vp[1];
            ctx2[0]  = ffma2(b0, vA.x, ctx2[0]);  ctx2[1]  = ffma2(b0, vA.y, ctx2[1]);
            ctx2[2]  = ffma2(b0, vB.x, ctx2[2]);  ctx2[3]  = ffma2(b0, vB.y, ctx2[3]);
            ctx2[4]  = ffma2(b1, vA.x, ctx2[4]);  ctx2[5]  = ffma2(b1, vA.y, ctx2[5]);
            ctx2[6]  = ffma2(b1, vB.x, ctx2[6]);  ctx2[7]  = ffma2(b1, vB.y, ctx2[7]);
            ctx2[8]  = ffma2(b2, vA.x, ctx2[8]);  ctx2[9]  = ffma2(b2, vA.y, ctx2[9]);
            ctx2[10] = ffma2(b2, vB.x, ctx2[10]); ctx2[11] = ffma2(b2, vB.y, ctx2[11]);
            ctx2[12] = ffma2(b3, vA.x, ctx2[12]); ctx2[13] = ffma2(b3, vA.y, ctx2[13]);
            ctx2[14] = ffma2(b3, vB.x, ctx2[14]); ctx2[15] = ffma2(b3, vB.y, ctx2[15]);
        }
    }

    __syncthreads();   // done with kps as kp buffer; reuse for ksum reduce

    // Write ctx partials: feature f = fbase + lane*4 + j, e = w*8..+7.
    {
        float* base = g_ctx_part + ((size_t)(bh * CH + chunk) * MFEAT) * DHEAD;
        #pragma unroll
        for (int j = 0; j < 4; j++) {
            float* op = base + (size_t)(fbase + lane * 4 + j) * DHEAD + w * 8;
            ((ulonglong2*)op)[0] = make_ulonglong2(ctx2[j * 4 + 0], ctx2[j * 4 + 1]);
            ((ulonglong2*)op)[1] = make_ulonglong2(ctx2[j * 4 + 2], ctx2[j * 4 + 3]);
        }
    }

    // ksum: warp partials -> cross-warp reduce through kps area.
    *(float4*)(kps + w * 128 + lane * 4) = make_float4(ks0, ks1, ks2, ks3);
    __syncthreads();
    if (t < 128) {
        float s = 0.f;
        #pragma unroll
        for (int w2 = 0; w2 < 8; w2++) s += kps[w2 * 128 + t];
        g_ksum_part[(bh * CH + chunk) * MFEAT + fbase + t] = s;
    }
    if (t == 0) g_lmax[(bh * CH + chunk) * 2 + fh] = M;
}

// ---------------------------------------------------------------------------
// vsum[bh][e] = sum_n V[bh][n][e]
// ---------------------------------------------------------------------------
__global__ __launch_bounds__(256) void kvsum(const float* __restrict__ V) {
    __shared__ float psum[16][64];
    const int bh = blockIdx.x, t = threadIdx.x;
    const int e4 = t & 15, rc = t >> 4;
    const float4* vb = (const float4*)V + (size_t)bh * NSEQ * 16;
    float4 acc = make_float4(0.f, 0.f, 0.f, 0.f);
    #pragma unroll 8
    for (int it = 0; it < 256; it++) {
        float4 a = vb[(size_t)(rc + 16 * it) * 16 + e4];
        acc.x += a.x; acc.y += a.y; acc.z += a.z; acc.w += a.w;
    }
    psum[rc][e4*4+0] = acc.x; psum[rc][e4*4+1] = acc.y;
    psum[rc][e4*4+2] = acc.z; psum[rc][e4*4+3] = acc.w;
    __syncthreads();
    if (t < 64) {
        float s = 0.f;
        #pragma unroll
        for (int r = 0; r < 16; r++) s += psum[r][t];
        g_vsum[bh * 64 + t] = s;
    }
}

// ---------------------------------------------------------------------------
// Per-bh global stab + per-(chunk,fh) scale factors.
// ---------------------------------------------------------------------------
__global__ void kscale() {
    const int bh = threadIdx.x;  // 64 threads
    float mx = -1e30f;
    #pragma unroll
    for (int c = 0; c < CH * 2; c++) mx = fmaxf(mx, g_lmax[bh * CH * 2 + c]);
    #pragma unroll
    for (int c = 0; c < CH * 2; c++)
        g_scale[bh * CH * 2 + c] = __expf(g_lmax[bh * CH * 2 + c] - mx);
}

// ---------------------------------------------------------------------------
// Reduce partials with rescale; add eps terms; apply RATIO.
// ---------------------------------------------------------------------------
__global__ void k2_reduce() {
    const size_t NCTX = (size_t)BH * MFEAT * DHEAD;  // 1048576
    size_t idx = (size_t)blockIdx.x * 256 + threadIdx.x;
    if (idx < NCTX) {
        size_t bh = idx >> 14;
        size_t rem = idx & 16383;
        size_t feat = rem >> 6;
        size_t fh = feat >> 7;
        size_t e = idx & 63;
        float s = 0.f;
        #pragma unroll
        for (int c = 0; c < CH; c++)
            s += g_scale[bh * CH * 2 + c * 2 + fh] *
                 g_ctx_part[(((size_t)bh * CH + c) << 14) + rem];
        g_ctx[idx] = RATIO * (s + KEPS * g_vsum[(bh << 6) + e]);
    } else if (idx < NCTX + (size_t)BH * MFEAT) {
        size_t i2 = idx - NCTX;
        size_t bh = i2 >> 8, j = i2 & 255;
        size_t fh = j >> 7;
        float s = 0.f;
        #pragma unroll
        for (int c = 0; c < CH; c++)
            s += g_scale[bh * CH * 2 + c * 2 + fh] *
                 g_ksum_part[(bh * CH + c) * MFEAT + j];
        g_ksum[i2] = RATIO * (s + KEPS * (float)NSEQ);
    }
}

// ---------------------------------------------------------------------------
// k3: q features + D_inv + output GEMM. 64-row tiles, ctx from L2, 2 CTAs/SM.
// Dyn smem: dds[64][260] @0 (66560B) + qsm[64][64] @66560 (16384B) = 82944B.
// ---------------------------------------------------------------------------
#define K3_SMEM_BYTES 82944

__global__ __launch_bounds__(256, 2) void k3_out(const float* __restrict__ Q,
                                                 const float* __restrict__ P,
                                                 float* __restrict__ O) {
    extern __shared__ __align__(16) char smraw[];
    float (*dds)[260] = (float (*)[260])smraw;            // [64][260]
    float (*qsm)[64]  = (float (*)[64])(smraw + 66560);   // [64][64]
    __shared__ float ksum_s[256];
    __shared__ float diag[64];
    __shared__ float rmax[64];
    __shared__ float dinv[64];

    const int bh = blockIdx.y, tile = blockIdx.x, t = threadIdx.x;
    const int w = t >> 5, lane = t & 31;

    u64 p2[32];
    {
        const ulonglong2* pr = (const ulonglong2*)(P + t * 64);
        #pragma unroll
        for (int i = 0; i < 16; i++) { ulonglong2 tt = pr[i]; p2[2*i] = tt.x; p2[2*i+1] = tt.y; }
    }
    ksum_s[t] = g_ksum[bh * MFEAT + t];

    // Load Q tile (64 x 64) + per-row diag via 16-lane shuffles.
    {
        const float4* qb = (const float4*)(Q + ((size_t)bh * NSEQ + (size_t)tile * 64) * DHEAD);
        float4* qs = (float4*)&qsm[0][0];
        #pragma unroll
        for (int kq = 0; kq < 4; kq++) {
            int i = t + 256 * kq;          // float4 index; row = i >> 4
            float4 a = qb[i];
            qs[i] = a;
            float ss = a.x*a.x + a.y*a.y + a.z*a.z + a.w*a.w;
            #pragma unroll
            for (int o = 1; o < 16; o <<= 1) ss += __shfl_xor_sync(0xffffffffu, ss, o);
            if ((t & 15) == 0) diag[i >> 4] = HALF_DN2 * ss;
        }
    }
    __syncthreads();

    // dd[r][t] = DN * dot(q[r], proj[t])
    #pragma unroll 2
    for (int r = 0; r < 64; r++) {
        const ulonglong2* qrow = (const ulonglong2*)qsm[r];
        u64 acc0 = 0, acc1 = 0, acc2 = 0, acc3 = 0;
        #pragma unroll
        for (int i = 0; i < 8; i++) {
            ulonglong2 qa = qrow[2*i];
            ulonglong2 qb2 = qrow[2*i+1];
            acc0 = ffma2(qa.x,  p2[4*i],   acc0);
            acc1 = ffma2(qa.y,  p2[4*i+1], acc1);
            acc2 = ffma2(qb2.x, p2[4*i+2], acc2);
            acc3 = ffma2(qb2.y, p2[4*i+3], acc3);
        }
        float2 f0 = unpack2(acc0), f1 = unpack2(acc1);
        float2 f2 = unpack2(acc2), f3 = unpack2(acc3);
        float s = ((f0.x + f0.y) + (f1.x + f1.y)) + ((f2.x + f2.y) + (f3.x + f3.y));
        dds[r][t] = DN * s;
    }
    __syncthreads();

    // Per-row max (8 rows per warp).
    #pragma unroll
    for (int rr = 0; rr < 8; rr++) {
        int r = w * 8 + rr;
        float m = dds[r][lane];
        #pragma unroll
        for (int c = 1; c < 8; c++) m = fmaxf(m, dds[r][lane + 32 * c]);
        #pragma unroll
        for (int o = 16; o; o >>= 1) m = fmaxf(m, __shfl_xor_sync(0xffffffffu, m, o));
        if (lane == 0) rmax[r] = m;
    }
    __syncthreads();

    // q' in place.
    #pragma unroll 4
    for (int r = 0; r < 64; r++)
        dds[r][t] = RATIO * (__expf(dds[r][t] - diag[r] - rmax[r]) + KEPS);
    __syncthreads();

    // D_inv (8 rows per warp).
    #pragma unroll
    for (int rr = 0; rr < 8; rr++) {
        int r = w * 8 + rr;
        float s = 0.f;
        #pragma unroll
        for (int c = 0; c < 8; c++)
            s = fmaf(dds[r][lane + 32 * c], ksum_s[lane + 32 * c], s);
        #pragma unroll
        for (int o = 16; o; o >>= 1) s += __shfl_xor_sync(0xffffffffu, s, o);
        if (lane == 0) dinv[r] = 1.0f / s;
    }
    __syncthreads();

    // out: 2 rows x 8 cols per thread; ctx streamed from global (L2-resident).
    const int rs = t >> 3;            // rows rs, rs+32
    const int ecg = (t & 7) * 2;      // ulonglong2 index within 64-float row
    const ulonglong2* cc = (const ulonglong2*)(g_ctx + (size_t)bh * MFEAT * DHEAD);
    u64 a0[4], a1[4];
    #pragma unroll
    for (int i = 0; i < 4; i++) { a0[i] = 0ull; a1[i] = 0ull; }
    #pragma unroll 4
    for (int jj = 0; jj < 256; jj++) {
        // 64-float ctx row = 16 ulonglong2 -> row stride 16.
        ulonglong2 cA = cc[jj * 16 + ecg];
        ulonglong2 cB = cc[jj * 16 + ecg + 1];
        float v0 = dds[rs][jj];
        float v1 = dds[rs + 32][jj];
        u64 q0 = pack2(v0, v0), q1 = pack2(v1, v1);
        a0[0] = ffma2(q0, cA.x, a0[0]); a0[1] = ffma2(q0, cA.y, a0[1]);
        a0[2] = ffma2(q0, cB.x, a0[2]); a0[3] = ffma2(q0, cB.y, a0[3]);
        a1[0] = ffma2(q1, cA.x, a1[0]); a1[1] = ffma2(q1, cA.y, a1[1]);
        a1[2] = ffma2(q1, cB.x, a1[2]); a1[3] = ffma2(q1, cB.y, a1[3]);
    }
    const size_t rowbase = (size_t)bh * NSEQ + (size_t)tile * 64;
    {
        u64 d2 = pack2(dinv[rs], dinv[rs]);
        float* ob = O + (rowbase + rs) * DHEAD + (size_t)ecg * 4;
        ((ulonglong2*)ob)[0] = make_ulonglong2(fmul2(a0[0], d2), fmul2(a0[1], d2));
        ((ulonglong2*)ob)[1] = make_ulonglong2(fmul2(a0[2], d2), fmul2(a0[3], d2));
        d2 = pack2(dinv[rs + 32], dinv[rs + 32]);
        ob = O + (rowbase + rs + 32) * DHEAD + (size_t)ecg * 4;
        ((ulonglong2*)ob)[0] = make_ulonglong2(fmul2(a1[0], d2), fmul2(a1[1], d2));
        ((ulonglong2*)ob)[1] = make_ulonglong2(fmul2(a1[2], d2), fmul2(a1[3], d2));
    }
}

// ---------------------------------------------------------------------------
extern "C" void kernel_launch(void* const* d_in, const int* in_sizes, int n_in,
                              void* d_out, int out_size) {
    const float* q    = (const float*)d_in[0];
    const float* k    = (const float*)d_in[1];
    const float* v    = (const float*)d_in[2];
    const float* proj = (const float*)d_in[3];
    float* out = (float*)d_out;

    cudaFuncSetAttribute(k12_ctx, cudaFuncAttributeMaxDynamicSharedMemorySize, K12_SMEM);
    cudaFuncSetAttribute(k3_out, cudaFuncAttributeMaxDynamicSharedMemorySize, K3_SMEM_BYTES);

    k12_ctx<<<dim3(CH * 2, BH), 256, K12_SMEM>>>(k, v, proj);
    kvsum<<<BH, 256>>>(v);
    kscale<<<1, BH>>>();
    {
        const size_t total = (size_t)BH * MFEAT * DHEAD + (size_t)BH * MFEAT;
        k2_reduce<<<(unsigned)((total + 255) / 256), 256>>>();
    }
    k3_out<<<dim3(NSEQ / 64, BH), 256, K3_SMEM_BYTES>>>(q, proj, out);
}

// round 9
// speedup vs baseline: 1.0510x; 1.0198x over previous
#include <cuda_runtime.h>
#include <cstdint>
#include <math.h>

// Problem constants
#define BH 64
#define NSEQ 4096
#define DHEAD 64
#define MFEAT 256
#define DN 0.3535533905932738f   // 64^-0.25
#define HALF_DN2 0.0625f          // 0.5 * 64^-0.5
#define RATIO 0.0625f             // 256^-0.5
#define KEPS 1e-4f
#define CH 16                     // row-chunks for k12 (256 rows each)
#define STAGES 8                  // 256/32 rows per stage

typedef unsigned long long u64;

// Packed fp32x2 helpers
__device__ __forceinline__ u64 ffma2(u64 a, u64 b, u64 c) {
    u64 d;
    asm("fma.rn.f32x2 %0, %1, %2, %3;" : "=l"(d) : "l"(a), "l"(b), "l"(c));
    return d;
}
__device__ __forceinline__ u64 fmul2(u64 a, u64 b) {
    u64 d;
    asm("mul.rn.f32x2 %0, %1, %2;" : "=l"(d) : "l"(a), "l"(b));
    return d;
}
__device__ __forceinline__ u64 pack2(float lo, float hi) {
    u64 d; asm("mov.b64 %0, {%1, %2};" : "=l"(d) : "f"(lo), "f"(hi)); return d;
}
__device__ __forceinline__ float2 unpack2(u64 v) {
    float lo, hi; asm("mov.b64 {%0, %1}, %2;" : "=f"(lo), "=f"(hi) : "l"(v));
    return make_float2(lo, hi);
}

// cp.async helpers
__device__ __forceinline__ void cp_async16(uint32_t s, const void* g) {
    asm volatile("cp.async.cg.shared.global [%0], [%1], 16;" :: "r"(s), "l"(g));
}
__device__ __forceinline__ void cp_commit() {
    asm volatile("cp.async.commit_group;" ::: "memory");
}
__device__ __forceinline__ void cp_wait0() {
    asm volatile("cp.async.wait_group 0;" ::: "memory");
}
template<int N> __device__ __forceinline__ void cp_wait() {
    asm volatile("cp.async.wait_group %0;" :: "n"(N) : "memory");
}

// Scratch (device globals). All entries fully rewritten each call.
__device__ float g_ctx_part[(size_t)BH * CH * MFEAT * DHEAD]; // 67 MB
__device__ float g_ksum_part[BH * CH * MFEAT];
__device__ float g_lmax[BH * CH * 2];
__device__ float g_scale[BH * CH * 2];
__device__ float g_vsum[BH * DHEAD];
__device__ float g_ctx[(size_t)BH * MFEAT * DHEAD];           // 4 MB
__device__ float g_ksum[BH * MFEAT];

// ---------------------------------------------------------------------------
// k12: fused K-features + partial ctx/ksum, outer-product form, 2 CTAs/SM.
// Grid (CH*2, BH): blockIdx.x = chunk*2 + fh; CTA owns 128 features, 256 rows.
// ---------------------------------------------------------------------------
#define K12_SMEM 84480

__global__ __launch_bounds__(256, 2) void k12_ctx(const float* __restrict__ K,
                                                  const float* __restrict__ V,
                                                  const float* __restrict__ P) {
    extern __shared__ __align__(16) char smraw[];
    float* Pt  = (float*)smraw;                    // [64][132]
    float* Ks  = (float*)(smraw + 33792);          // [2][32][68]
    float* Vs  = (float*)(smraw + 51200);          // [2][32][64]
    float* kps = (float*)(smraw + 67584);          // [32][132]
    __shared__ float wmax[8];

    const int bh = blockIdx.y;
    const int chunk = blockIdx.x >> 1;
    const int fh = blockIdx.x & 1;
    const int fbase = fh * 128;
    const int t = threadIdx.x;
    const int w = t >> 5, lane = t & 31;

    const float* kb = K + ((size_t)bh * NSEQ + (size_t)chunk * 256) * 64;
    const float* vb = V + ((size_t)bh * NSEQ + (size_t)chunk * 256) * 64;

    uint32_t ks_s = (uint32_t)__cvta_generic_to_shared(Ks);
    uint32_t vs_s = (uint32_t)__cvta_generic_to_shared(Vs);

    // Prologue: stage 0 (buf 0).
    {
        int c0 = t, c1 = t + 256;
        int r0 = c0 >> 4, q0 = c0 & 15, r1 = c1 >> 4, q1 = c1 & 15;
        cp_async16(ks_s + r0 * 272 + q0 * 16, kb + r0 * 64 + q0 * 4);
        cp_async16(ks_s + r1 * 272 + q1 * 16, kb + r1 * 64 + q1 * 4);
        cp_async16(vs_s + r0 * 256 + q0 * 16, vb + r0 * 64 + q0 * 4);
        cp_async16(vs_s + r1 * 256 + q1 * 16, vb + r1 * 64 + q1 * 4);
        cp_commit();
    }

    // Load P slice transposed: Pt[d][f] = P[fbase+f][d], f in [0,128).
    for (int idx = t; idx < 128 * 64; idx += 256) {
        int f = idx >> 6, d = idx & 63;
        Pt[d * 132 + f] = P[(size_t)(fbase + f) * 64 + d];
    }

    u64 ctx2[16];          // [4 features][4 e-pairs] -> f = lane*4+j, e = w*8..+7
    #pragma unroll
    for (int i = 0; i < 16; i++) ctx2[i] = 0ull;
    float ks0 = 0.f, ks1 = 0.f, ks2 = 0.f, ks3 = 0.f;
    float M = -1e30f;

    for (int st = 0; st < STAGES; st++) {
        const int buf = st & 1;
        cp_wait0();
        __syncthreads();

        if (st + 1 < STAGES) {
            const float* kn = kb + (st + 1) * 32 * 64;
            const float* vn = vb + (st + 1) * 32 * 64;
            uint32_t kd = ks_s + (buf ^ 1) * 8704;
            uint32_t vd = vs_s + (buf ^ 1) * 8192;
            int c0 = t, c1 = t + 256;
            int r0 = c0 >> 4, q0 = c0 & 15, r1 = c1 >> 4, q1 = c1 & 15;
            cp_async16(kd + r0 * 272 + q0 * 16, kn + r0 * 64 + q0 * 4);
            cp_async16(kd + r1 * 272 + q1 * 16, kn + r1 * 64 + q1 * 4);
            cp_async16(vd + r0 * 256 + q0 * 16, vn + r0 * 64 + q0 * 4);
            cp_async16(vd + r1 * 256 + q1 * 16, vn + r1 * 64 + q1 * 4);
            cp_commit();
        }

        const float* ksb = Ks + buf * 2176;   // floats
        const float* vsb = Vs + buf * 2048;

        // diag for this warp's 4 rows.
        float diag_r[4];
        #pragma unroll
        for (int i = 0; i < 4; i++) {
            const float* kr = ksb + (w * 4 + i) * 68;
            float2 v2 = *(const float2*)(kr + 2 * lane);
            float ss = v2.x * v2.x + v2.y * v2.y;
            #pragma unroll
            for (int o = 16; o; o >>= 1) ss += __shfl_xor_sync(0xffffffffu, ss, o);
            diag_r[i] = HALF_DN2 * ss;
        }

        // dd outer product: rows w*4..+3  x  features lane*4..+3.
        u64 acc[4][2];
        #pragma unroll
        for (int i = 0; i < 4; i++) { acc[i][0] = 0ull; acc[i][1] = 0ull; }
        const float* kr0 = ksb + (w * 4 + 0) * 68;
        const float* kr1 = ksb + (w * 4 + 1) * 68;
        const float* kr2 = ksb + (w * 4 + 2) * 68;
        const float* kr3 = ksb + (w * 4 + 3) * 68;
        #pragma unroll 4
        for (int d = 0; d < 64; d += 4) {
            float4 k0 = *(const float4*)(kr0 + d);
            float4 k1 = *(const float4*)(kr1 + d);
            float4 k2 = *(const float4*)(kr2 + d);
            float4 k3 = *(const float4*)(kr3 + d);
            #pragma unroll
            for (int q = 0; q < 4; q++) {
                ulonglong2 pv = *(const ulonglong2*)(Pt + (d + q) * 132 + lane * 4);
                float kq0 = (q == 0) ? k0.x : (q == 1) ? k0.y : (q == 2) ? k0.z : k0.w;
                float kq1 = (q == 0) ? k1.x : (q == 1) ? k1.y : (q == 2) ? k1.z : k1.w;
                float kq2 = (q == 0) ? k2.x : (q == 1) ? k2.y : (q == 2) ? k2.z : k2.w;
                float kq3 = (q == 0) ? k3.x : (q == 1) ? k3.y : (q == 2) ? k3.z : k3.w;
                u64 b0 = pack2(kq0, kq0), b1 = pack2(kq1, kq1);
                u64 b2 = pack2(kq2, kq2), b3 = pack2(kq3, kq3);
                acc[0][0] = ffma2(b0, pv.x, acc[0][0]); acc[0][1] = ffma2(b0, pv.y, acc[0][1]);
                acc[1][0] = ffma2(b1, pv.x, acc[1][0]); acc[1][1] = ffma2(b1, pv.y, acc[1][1]);
                acc[2][0] = ffma2(b2, pv.x, acc[2][0]); acc[2][1] = ffma2(b2, pv.y, acc[2][1]);
                acc[3][0] = ffma2(b3, pv.x, acc[3][0]); acc[3][1] = ffma2(b3, pv.y, acc[3][1]);
            }
        }

        // dd values, local max.
        float dd[4][4];
        float mx = -1e30f;
        #pragma unroll
        for (int i = 0; i < 4; i++) {
            float2 lo = unpack2(acc[i][0]);
            float2 hi = unpack2(acc[i][1]);
            dd[i][0] = DN * lo.x; dd[i][1] = DN * lo.y;
            dd[i][2] = DN * hi.x; dd[i][3] = DN * hi.y;
            mx = fmaxf(mx, fmaxf(fmaxf(dd[i][0], dd[i][1]), fmaxf(dd[i][2], dd[i][3])));
        }
        #pragma unroll
        for (int o = 16; o; o >>= 1) mx = fmaxf(mx, __shfl_xor_sync(0xffffffffu, mx, o));
        if (lane == 0) wmax[w] = mx;
        __syncthreads();
        float smax = wmax[0];
        #pragma unroll
        for (int i = 1; i < 8; i++) smax = fmaxf(smax, wmax[i]);

        if (smax > M) {   // CTA-uniform
            float sc = __expf(M - smax);
            u64 sc2 = pack2(sc, sc);
            #pragma unroll
            for (int i = 0; i < 16; i++) ctx2[i] = fmul2(ctx2[i], sc2);
            ks0 *= sc; ks1 *= sc; ks2 *= sc; ks3 *= sc;
            M = smax;
        }

        // exp in regs, accumulate ksum, store kp tile to shared.
        #pragma unroll
        for (int i = 0; i < 4; i++) {
            float k0 = __expf(dd[i][0] - diag_r[i] - M);
            float k1 = __expf(dd[i][1] - diag_r[i] - M);
            float k2 = __expf(dd[i][2] - diag_r[i] - M);
            float k3 = __expf(dd[i][3] - diag_r[i] - M);
            ks0 += k0; ks1 += k1; ks2 += k2; ks3 += k3;
            *(float4*)(kps + (w * 4 + i) * 132 + lane * 4) = make_float4(k0, k1, k2, k3);
        }
        __syncthreads();

        // ctx outer product: features lane*4..+3  x  e-cols w*8..+7.
        #pragma unroll 4
        for (int r = 0; r < 32; r++) {
            ulonglong2 kp4 = *(const ulonglong2*)(kps + r * 132 + lane * 4);
            float2 klo = unpack2(kp4.x), khi = unpack2(kp4.y);
            u64 b0 = pack2(klo.x, klo.x), b1 = pack2(klo.y, klo.y);
            u64 b2 = pack2(khi.x, khi.x), b3 = pack2(khi.y, khi.y);
            const ulonglong2* vp = (const ulonglong2*)(vsb + r * 64 + w * 8);
            ulonglong2 vA = vp[0], vB = vp[1];
            ctx2[0]  = ffma2(b0, vA.x, ctx2[0]);  ctx2[1]  = ffma2(b0, vA.y, ctx2[1]);
            ctx2[2]  = ffma2(b0, vB.x, ctx2[2]);  ctx2[3]  = ffma2(b0, vB.y, ctx2[3]);
            ctx2[4]  = ffma2(b1, vA.x, ctx2[4]);  ctx2[5]  = ffma2(b1, vA.y, ctx2[5]);
            ctx2[6]  = ffma2(b1, vB.x, ctx2[6]);  ctx2[7]  = ffma2(b1, vB.y, ctx2[7]);
            ctx2[8]  = ffma2(b2, vA.x, ctx2[8]);  ctx2[9]  = ffma2(b2, vA.y, ctx2[9]);
            ctx2[10] = ffma2(b2, vB.x, ctx2[10]); ctx2[11] = ffma2(b2, vB.y, ctx2[11]);
            ctx2[12] = ffma2(b3, vA.x, ctx2[12]); ctx2[13] = ffma2(b3, vA.y, ctx2[13]);
            ctx2[14] = ffma2(b3, vB.x, ctx2[14]); ctx2[15] = ffma2(b3, vB.y, ctx2[15]);
        }
    }

    __syncthreads();   // done with kps as kp buffer; reuse for ksum reduce

    // Write ctx partials: feature f = fbase + lane*4 + j, e = w*8..+7.
    {
        float* base = g_ctx_part + ((size_t)(bh * CH + chunk) * MFEAT) * DHEAD;
        #pragma unroll
        for (int j = 0; j < 4; j++) {
            float* op = base + (size_t)(fbase + lane * 4 + j) * DHEAD + w * 8;
            ((ulonglong2*)op)[0] = make_ulonglong2(ctx2[j * 4 + 0], ctx2[j * 4 + 1]);
            ((ulonglong2*)op)[1] = make_ulonglong2(ctx2[j * 4 + 2], ctx2[j * 4 + 3]);
        }
    }

    // ksum: warp partials -> cross-warp reduce through kps area.
    *(float4*)(kps + w * 128 + lane * 4) = make_float4(ks0, ks1, ks2, ks3);
    __syncthreads();
    if (t < 128) {
        float s = 0.f;
        #pragma unroll
        for (int w2 = 0; w2 < 8; w2++) s += kps[w2 * 128 + t];
        g_ksum_part[(bh * CH + chunk) * MFEAT + fbase + t] = s;
    }
    if (t == 0) g_lmax[(bh * CH + chunk) * 2 + fh] = M;
}

// ---------------------------------------------------------------------------
// vsum[bh][e] = sum_n V[bh][n][e]
// ---------------------------------------------------------------------------
__global__ __launch_bounds__(256) void kvsum(const float* __restrict__ V) {
    __shared__ float psum[16][64];
    const int bh = blockIdx.x, t = threadIdx.x;
    const int e4 = t & 15, rc = t >> 4;
    const float4* vb = (const float4*)V + (size_t)bh * NSEQ * 16;
    float4 acc = make_float4(0.f, 0.f, 0.f, 0.f);
    #pragma unroll 8
    for (int it = 0; it < 256; it++) {
        float4 a = vb[(size_t)(rc + 16 * it) * 16 + e4];
        acc.x += a.x; acc.y += a.y; acc.z += a.z; acc.w += a.w;
    }
    psum[rc][e4*4+0] = acc.x; psum[rc][e4*4+1] = acc.y;
    psum[rc][e4*4+2] = acc.z; psum[rc][e4*4+3] = acc.w;
    __syncthreads();
    if (t < 64) {
        float s = 0.f;
        #pragma unroll
        for (int r = 0; r < 16; r++) s += psum[r][t];
        g_vsum[bh * 64 + t] = s;
    }
}

// ---------------------------------------------------------------------------
// Per-bh global stab + per-(chunk,fh) scale factors.
// ---------------------------------------------------------------------------
__global__ void kscale() {
    const int bh = threadIdx.x;  // 64 threads
    float mx = -1e30f;
    #pragma unroll
    for (int c = 0; c < CH * 2; c++) mx = fmaxf(mx, g_lmax[bh * CH * 2 + c]);
    #pragma unroll
    for (int c = 0; c < CH * 2; c++)
        g_scale[bh * CH * 2 + c] = __expf(g_lmax[bh * CH * 2 + c] - mx);
}

// ---------------------------------------------------------------------------
// Reduce partials with rescale; add eps terms; apply RATIO.
// ---------------------------------------------------------------------------
__global__ void k2_reduce() {
    const size_t NCTX = (size_t)BH * MFEAT * DHEAD;  // 1048576
    size_t idx = (size_t)blockIdx.x * 256 + threadIdx.x;
    if (idx < NCTX) {
        size_t bh = idx >> 14;
        size_t rem = idx & 16383;
        size_t feat = rem >> 6;
        size_t fh = feat >> 7;
        size_t e = idx & 63;
        float s = 0.f;
        #pragma unroll
        for (int c = 0; c < CH; c++)
            s += g_scale[bh * CH * 2 + c * 2 + fh] *
                 g_ctx_part[(((size_t)bh * CH + c) << 14) + rem];
        g_ctx[idx] = RATIO * (s + KEPS * g_vsum[(bh << 6) + e]);
    } else if (idx < NCTX + (size_t)BH * MFEAT) {
        size_t i2 = idx - NCTX;
        size_t bh = i2 >> 8, j = i2 & 255;
        size_t fh = j >> 7;
        float s = 0.f;
        #pragma unroll
        for (int c = 0; c < CH; c++)
            s += g_scale[bh * CH * 2 + c * 2 + fh] *
                 g_ksum_part[(bh * CH + c) * MFEAT + j];
        g_ksum[i2] = RATIO * (s + KEPS * (float)NSEQ);
    }
}

// ---------------------------------------------------------------------------
// k3: q features + D_inv + output GEMM. 64-row tiles, 2 CTAs/SM.
// ctx staged through shared in 4 chunks (cp.async double buffer) — removes
// the L2-latency-bound LDG stream in the out-GEMM.
// Dyn smem: dds[64][260] @0 (66560B) + overlay @66560:
//   phase 1: qsm[64][64] (16384B); phase 2: ctx stage bufs 2x16384B.
// total 66560 + 32768 = 99328B.
// ---------------------------------------------------------------------------
#define K3_SMEM_BYTES (66560 + 32768)

__global__ __launch_bounds__(256, 2) void k3_out(const float* __restrict__ Q,
                                                 const float* __restrict__ P,
                                                 float* __restrict__ O) {
    extern __shared__ __align__(16) char smraw[];
    float (*dds)[260] = (float (*)[260])smraw;            // [64][260]
    float* ovl  = (float*)(smraw + 66560);
    float (*qsm)[64] = (float (*)[64])ovl;                // phase 1 only
    float* ctxs = ovl;                                    // phase 2: 2 x 4096 floats
    __shared__ float ksum_s[256];
    __shared__ float diag[64];
    __shared__ float rmax[64];
    __shared__ float dinv[64];

    const int bh = blockIdx.y, tile = blockIdx.x, t = threadIdx.x;
    const int w = t >> 5, lane = t & 31;

    u64 p2[32];
    {
        const ulonglong2* pr = (const ulonglong2*)(P + t * 64);
        #pragma unroll
        for (int i = 0; i < 16; i++) { ulonglong2 tt = pr[i]; p2[2*i] = tt.x; p2[2*i+1] = tt.y; }
    }
    ksum_s[t] = g_ksum[bh * MFEAT + t];

    // Load Q tile (64 x 64) + per-row diag via 16-lane shuffles.
    {
        const float4* qb = (const float4*)(Q + ((size_t)bh * NSEQ + (size_t)tile * 64) * DHEAD);
        float4* qs = (float4*)&qsm[0][0];
        #pragma unroll
        for (int kq = 0; kq < 4; kq++) {
            int i = t + 256 * kq;          // float4 index; row = i >> 4
            float4 a = qb[i];
            qs[i] = a;
            float ss = a.x*a.x + a.y*a.y + a.z*a.z + a.w*a.w;
            #pragma unroll
            for (int o = 1; o < 16; o <<= 1) ss += __shfl_xor_sync(0xffffffffu, ss, o);
            if ((t & 15) == 0) diag[i >> 4] = HALF_DN2 * ss;
        }
    }
    __syncthreads();

    // dd[r][t] = DN * dot(q[r], proj[t])
    #pragma unroll 2
    for (int r = 0; r < 64; r++) {
        const ulonglong2* qrow = (const ulonglong2*)qsm[r];
        u64 acc0 = 0, acc1 = 0, acc2 = 0, acc3 = 0;
        #pragma unroll
        for (int i = 0; i < 8; i++) {
            ulonglong2 qa = qrow[2*i];
            ulonglong2 qb2 = qrow[2*i+1];
            acc0 = ffma2(qa.x,  p2[4*i],   acc0);
            acc1 = ffma2(qa.y,  p2[4*i+1], acc1);
            acc2 = ffma2(qb2.x, p2[4*i+2], acc2);
            acc3 = ffma2(qb2.y, p2[4*i+3], acc3);
        }
        float2 f0 = unpack2(acc0), f1 = unpack2(acc1);
        float2 f2 = unpack2(acc2), f3 = unpack2(acc3);
        float s = ((f0.x + f0.y) + (f1.x + f1.y)) + ((f2.x + f2.y) + (f3.x + f3.y));
        dds[r][t] = DN * s;
    }
    __syncthreads();   // qsm dead after this point

    // Prologue: stage ctx chunk 0 (features 0..63) into buf 0.
    const uint32_t ctx_s = (uint32_t)__cvta_generic_to_shared(ctxs);
    const float* cgb = g_ctx + (size_t)bh * MFEAT * DHEAD;
    {
        #pragma unroll
        for (int q = 0; q < 4; q++) {
            int i = t + 256 * q;                 // float4 index in 16KB chunk
            cp_async16(ctx_s + i * 16, cgb + i * 4);
        }
        cp_commit();
    }

    // Per-row max (8 rows per warp).
    #pragma unroll
    for (int rr = 0; rr < 8; rr++) {
        int r = w * 8 + rr;
        float m = dds[r][lane];
        #pragma unroll
        for (int c = 1; c < 8; c++) m = fmaxf(m, dds[r][lane + 32 * c]);
        #pragma unroll
        for (int o = 16; o; o >>= 1) m = fmaxf(m, __shfl_xor_sync(0xffffffffu, m, o));
        if (lane == 0) rmax[r] = m;
    }
    __syncthreads();

    // q' in place.
    #pragma unroll 4
    for (int r = 0; r < 64; r++)
        dds[r][t] = RATIO * (__expf(dds[r][t] - diag[r] - rmax[r]) + KEPS);
    __syncthreads();

    // D_inv (8 rows per warp).
    #pragma unroll
    for (int rr = 0; rr < 8; rr++) {
        int r = w * 8 + rr;
        float s = 0.f;
        #pragma unroll
        for (int c = 0; c < 8; c++)
            s = fmaf(dds[r][lane + 32 * c], ksum_s[lane + 32 * c], s);
        #pragma unroll
        for (int o = 16; o; o >>= 1) s += __shfl_xor_sync(0xffffffffu, s, o);
        if (lane == 0) dinv[r] = 1.0f / s;
    }

    // out: 2 rows x 8 cols per thread; ctx from shared, chunked 4 x 64 features.
    const int rs = t >> 3;            // rows rs, rs+32
    const int ecg = (t & 7) * 2;      // ulonglong2 index within 64-float row
    u64 a0[4], a1[4];
    #pragma unroll
    for (int i = 0; i < 4; i++) { a0[i] = 0ull; a1[i] = 0ull; }

    #pragma unroll
    for (int c = 0; c < 4; c++) {
        if (c + 1 < 4) {
            // prefetch chunk c+1 into buf (c+1)&1 (consumed two iterations ago)
            uint32_t dst = ctx_s + ((c + 1) & 1) * 16384;
            const float* src = cgb + (c + 1) * 4096;
            #pragma unroll
            for (int q = 0; q < 4; q++) {
                int i = t + 256 * q;
                cp_async16(dst + i * 16, src + i * 4);
            }
            cp_commit();
            cp_wait<1>();
        } else {
            cp_wait<0>();
        }
        __syncthreads();   // chunk c visible; also orders reuse of buffers

        const ulonglong2* cc = (const ulonglong2*)(ctxs + (c & 1) * 4096);
        #pragma unroll 4
        for (int jl = 0; jl < 64; jl++) {
            int jj = c * 64 + jl;
            ulonglong2 cA = cc[jl * 16 + ecg];
            ulonglong2 cB = cc[jl * 16 + ecg + 1];
            float v0 = dds[rs][jj];
            float v1 = dds[rs + 32][jj];
            u64 q0 = pack2(v0, v0), q1 = pack2(v1, v1);
            a0[0] = ffma2(q0, cA.x, a0[0]); a0[1] = ffma2(q0, cA.y, a0[1]);
            a0[2] = ffma2(q0, cB.x, a0[2]); a0[3] = ffma2(q0, cB.y, a0[3]);
            a1[0] = ffma2(q1, cA.x, a1[0]); a1[1] = ffma2(q1, cA.y, a1[1]);
            a1[2] = ffma2(q1, cB.x, a1[2]); a1[3] = ffma2(q1, cB.y, a1[3]);
        }
        __syncthreads();   // all warps done with buf (c&1) before it is refilled
    }

    const size_t rowbase = (size_t)bh * NSEQ + (size_t)tile * 64;
    {
        u64 d2 = pack2(dinv[rs], dinv[rs]);
        float* ob = O + (rowbase + rs) * DHEAD + (size_t)ecg * 4;
        ((ulonglong2*)ob)[0] = make_ulonglong2(fmul2(a0[0], d2), fmul2(a0[1], d2));
        ((ulonglong2*)ob)[1] = make_ulonglong2(fmul2(a0[2], d2), fmul2(a0[3], d2));
        d2 = pack2(dinv[rs + 32], dinv[rs + 32]);
        ob = O + (rowbase + rs + 32) * DHEAD + (size_t)ecg * 4;
        ((ulonglong2*)ob)[0] = make_ulonglong2(fmul2(a1[0], d2), fmul2(a1[1], d2));
        ((ulonglong2*)ob)[1] = make_ulonglong2(fmul2(a1[2], d2), fmul2(a1[3], d2));
    }
}

// ---------------------------------------------------------------------------
extern "C" void kernel_launch(void* const* d_in, const int* in_sizes, int n_in,
                              void* d_out, int out_size) {
    const float* q    = (const float*)d_in[0];
    const float* k    = (const float*)d_in[1];
    const float* v    = (const float*)d_in[2];
    const float* proj = (const float*)d_in[3];
    float* out = (float*)d_out;

    cudaFuncSetAttribute(k12_ctx, cudaFuncAttributeMaxDynamicSharedMemorySize, K12_SMEM);
    cudaFuncSetAttribute(k3_out, cudaFuncAttributeMaxDynamicSharedMemorySize, K3_SMEM_BYTES);

    k12_ctx<<<dim3(CH * 2, BH), 256, K12_SMEM>>>(k, v, proj);
    kvsum<<<BH, 256>>>(v);
    kscale<<<1, BH>>>();
    {
        const size_t total = (size_t)BH * MFEAT * DHEAD + (size_t)BH * MFEAT;
        k2_reduce<<<(unsigned)((total + 255) / 256), 256>>>();
    }
    k3_out<<<dim3(NSEQ / 64, BH), 256, K3_SMEM_BYTES>>>(q, proj, out);
}

// round 10
// speedup vs baseline: 1.0598x; 1.0084x over previous
#include <cuda_runtime.h>
#include <cstdint>
#include <math.h>

// Problem constants
#define BH 64
#define NSEQ 4096
#define DHEAD 64
#define MFEAT 256
#define RATIO 0.0625f             // 256^-0.5
#define KEPS 1e-4f
#define CH 16                     // row-chunks for k12 (256 rows each)
#define STAGES 8                  // 256/32 rows per stage

// log2-domain constants: dd' = dd*log2e via pre-scaled proj; diag' = diag*log2e
#define DN_L2E   0.510069723f     // 64^-0.25 * log2(e)
#define HDN2_L2E 0.0901684401f    // 0.5 * 64^-0.5 * log2(e)

typedef unsigned long long u64;

// Packed fp32x2 helpers
__device__ __forceinline__ u64 ffma2(u64 a, u64 b, u64 c) {
    u64 d;
    asm("fma.rn.f32x2 %0, %1, %2, %3;" : "=l"(d) : "l"(a), "l"(b), "l"(c));
    return d;
}
__device__ __forceinline__ u64 fmul2(u64 a, u64 b) {
    u64 d;
    asm("mul.rn.f32x2 %0, %1, %2;" : "=l"(d) : "l"(a), "l"(b));
    return d;
}
__device__ __forceinline__ u64 fadd2(u64 a, u64 b) {
    u64 d;
    asm("add.rn.f32x2 %0, %1, %2;" : "=l"(d) : "l"(a), "l"(b));
    return d;
}
__device__ __forceinline__ u64 pack2(float lo, float hi) {
    u64 d; asm("mov.b64 %0, {%1, %2};" : "=l"(d) : "f"(lo), "f"(hi)); return d;
}
__device__ __forceinline__ float2 unpack2(u64 v) {
    float lo, hi; asm("mov.b64 {%0, %1}, %2;" : "=f"(lo), "=f"(hi) : "l"(v));
    return make_float2(lo, hi);
}

// Packed exp2 of two floats on the FMA pipe (degree-5 poly, rel err ~2e-6).
// Valid for y >= -120 (clamped); y <= 0 in our use.
__device__ __forceinline__ u64 exp2_poly2(float y0, float y1) {
    y0 = fmaxf(y0, -120.f);
    y1 = fmaxf(y1, -120.f);
    u64 y = pack2(y0, y1);
    const u64 C  = pack2(12582912.f, 12582912.f);    // 1.5*2^23
    const u64 nC = pack2(-12582912.f, -12582912.f);
    const u64 n1 = pack2(-1.f, -1.f);
    u64 z  = fadd2(y, C);                 // integer part in mantissa
    u64 iz = fadd2(z, nC);                // round(y) as float pair
    u64 f  = ffma2(iz, n1, y);            // y - round(y), in [-0.5, 0.5]
    u64 p  = pack2(0.00133335581f, 0.00133335581f);
    p = ffma2(p, f, pack2(0.00961812911f, 0.00961812911f));
    p = ffma2(p, f, pack2(0.05550410866f, 0.05550410866f));
    p = ffma2(p, f, pack2(0.24022650696f, 0.24022650696f));
    p = ffma2(p, f, pack2(0.69314718056f, 0.69314718056f));
    p = ffma2(p, f, pack2(1.f, 1.f));
    uint32_t zlo, zhi;
    asm("mov.b64 {%0,%1}, %2;" : "=r"(zlo), "=r"(zhi) : "l"(z));
    uint32_t slo = zlo * 8388608u + 0x3F800000u;     // (i+127)<<23
    uint32_t shi = zhi * 8388608u + 0x3F800000u;
    u64 s; asm("mov.b64 %0, {%1,%2};" : "=l"(s) : "r"(slo), "r"(shi));
    return fmul2(p, s);
}

// cp.async helpers
__device__ __forceinline__ void cp_async16(uint32_t s, const void* g) {
    asm volatile("cp.async.cg.shared.global [%0], [%1], 16;" :: "r"(s), "l"(g));
}
__device__ __forceinline__ void cp_commit() {
    asm volatile("cp.async.commit_group;" ::: "memory");
}
__device__ __forceinline__ void cp_wait0() {
    asm volatile("cp.async.wait_group 0;" ::: "memory");
}
template<int N> __device__ __forceinline__ void cp_wait() {
    asm volatile("cp.async.wait_group %0;" :: "n"(N) : "memory");
}

// Scratch (device globals). All entries fully rewritten each call.
__device__ float g_ctx_part[(size_t)BH * CH * MFEAT * DHEAD]; // 67 MB
__device__ float g_ksum_part[BH * CH * MFEAT];
__device__ float g_lmax[BH * CH * 2];     // log2-domain
__device__ float g_scale[BH * CH * 2];
__device__ float g_vsum[BH * DHEAD];
__device__ float g_ctx[(size_t)BH * MFEAT * DHEAD];           // 4 MB
__device__ float g_ksum[BH * MFEAT];

// ---------------------------------------------------------------------------
// k12: fused K-features + partial ctx/ksum, outer-product form, 2 CTAs/SM.
// Grid (CH*2, BH): blockIdx.x = chunk*2 + fh; CTA owns 128 features, 256 rows.
// All exponentials in log2 domain (proj pre-scaled by DN*log2e).
// ---------------------------------------------------------------------------
#define K12_SMEM 84480

__global__ __launch_bounds__(256, 2) void k12_ctx(const float* __restrict__ K,
                                                  const float* __restrict__ V,
                                                  const float* __restrict__ P) {
    extern __shared__ __align__(16) char smraw[];
    float* Pt  = (float*)smraw;                    // [64][132]
    float* Ks  = (float*)(smraw + 33792);          // [2][32][68]
    float* Vs  = (float*)(smraw + 51200);          // [2][32][64]
    float* kps = (float*)(smraw + 67584);          // [32][132]
    __shared__ float wmax[8];

    const int bh = blockIdx.y;
    const int chunk = blockIdx.x >> 1;
    const int fh = blockIdx.x & 1;
    const int fbase = fh * 128;
    const int t = threadIdx.x;
    const int w = t >> 5, lane = t & 31;

    const float* kb = K + ((size_t)bh * NSEQ + (size_t)chunk * 256) * 64;
    const float* vb = V + ((size_t)bh * NSEQ + (size_t)chunk * 256) * 64;

    uint32_t ks_s = (uint32_t)__cvta_generic_to_shared(Ks);
    uint32_t vs_s = (uint32_t)__cvta_generic_to_shared(Vs);

    // Prologue: stage 0 (buf 0).
    {
        int c0 = t, c1 = t + 256;
        int r0 = c0 >> 4, q0 = c0 & 15, r1 = c1 >> 4, q1 = c1 & 15;
        cp_async16(ks_s + r0 * 272 + q0 * 16, kb + r0 * 64 + q0 * 4);
        cp_async16(ks_s + r1 * 272 + q1 * 16, kb + r1 * 64 + q1 * 4);
        cp_async16(vs_s + r0 * 256 + q0 * 16, vb + r0 * 64 + q0 * 4);
        cp_async16(vs_s + r1 * 256 + q1 * 16, vb + r1 * 64 + q1 * 4);
        cp_commit();
    }

    // Load P slice transposed and pre-scaled: Pt[d][f] = DN_L2E * P[fbase+f][d].
    for (int idx = t; idx < 128 * 64; idx += 256) {
        int f = idx >> 6, d = idx & 63;
        Pt[d * 132 + f] = DN_L2E * P[(size_t)(fbase + f) * 64 + d];
    }

    u64 ctx2[16];          // [4 features][4 e-pairs] -> f = lane*4+j, e = w*8..+7
    #pragma unroll
    for (int i = 0; i < 16; i++) ctx2[i] = 0ull;
    float ks0 = 0.f, ks1 = 0.f, ks2 = 0.f, ks3 = 0.f;
    float M = -1e30f;

    for (int st = 0; st < STAGES; st++) {
        const int buf = st & 1;
        cp_wait0();
        __syncthreads();

        if (st + 1 < STAGES) {
            const float* kn = kb + (st + 1) * 32 * 64;
            const float* vn = vb + (st + 1) * 32 * 64;
            uint32_t kd = ks_s + (buf ^ 1) * 8704;
            uint32_t vd = vs_s + (buf ^ 1) * 8192;
            int c0 = t, c1 = t + 256;
            int r0 = c0 >> 4, q0 = c0 & 15, r1 = c1 >> 4, q1 = c1 & 15;
            cp_async16(kd + r0 * 272 + q0 * 16, kn + r0 * 64 + q0 * 4);
            cp_async16(kd + r1 * 272 + q1 * 16, kn + r1 * 64 + q1 * 4);
            cp_async16(vd + r0 * 256 + q0 * 16, vn + r0 * 64 + q0 * 4);
            cp_async16(vd + r1 * 256 + q1 * 16, vn + r1 * 64 + q1 * 4);
            cp_commit();
        }

        const float* ksb = Ks + buf * 2176;   // floats
        const float* vsb = Vs + buf * 2048;

        // diag (log2 domain) for this warp's 4 rows.
        float diag_r[4];
        #pragma unroll
        for (int i = 0; i < 4; i++) {
            const float* kr = ksb + (w * 4 + i) * 68;
            float2 v2 = *(const float2*)(kr + 2 * lane);
            float ss = v2.x * v2.x + v2.y * v2.y;
            #pragma unroll
            for (int o = 16; o; o >>= 1) ss += __shfl_xor_sync(0xffffffffu, ss, o);
            diag_r[i] = HDN2_L2E * ss;
        }

        // dd outer product: rows w*4..+3  x  features lane*4..+3.
        u64 acc[4][2];
        #pragma unroll
        for (int i = 0; i < 4; i++) { acc[i][0] = 0ull; acc[i][1] = 0ull; }
        const float* kr0 = ksb + (w * 4 + 0) * 68;
        const float* kr1 = ksb + (w * 4 + 1) * 68;
        const float* kr2 = ksb + (w * 4 + 2) * 68;
        const float* kr3 = ksb + (w * 4 + 3) * 68;
        #pragma unroll 4
        for (int d = 0; d < 64; d += 4) {
            float4 k0 = *(const float4*)(kr0 + d);
            float4 k1 = *(const float4*)(kr1 + d);
            float4 k2 = *(const float4*)(kr2 + d);
            float4 k3 = *(const float4*)(kr3 + d);
            #pragma unroll
            for (int q = 0; q < 4; q++) {
                ulonglong2 pv = *(const ulonglong2*)(Pt + (d + q) * 132 + lane * 4);
                float kq0 = (q == 0) ? k0.x : (q == 1) ? k0.y : (q == 2) ? k0.z : k0.w;
                float kq1 = (q == 0) ? k1.x : (q == 1) ? k1.y : (q == 2) ? k1.z : k1.w;
                float kq2 = (q == 0) ? k2.x : (q == 1) ? k2.y : (q == 2) ? k2.z : k2.w;
                float kq3 = (q == 0) ? k3.x : (q == 1) ? k3.y : (q == 2) ? k3.z : k3.w;
                u64 b0 = pack2(kq0, kq0), b1 = pack2(kq1, kq1);
                u64 b2 = pack2(kq2, kq2), b3 = pack2(kq3, kq3);
                acc[0][0] = ffma2(b0, pv.x, acc[0][0]); acc[0][1] = ffma2(b0, pv.y, acc[0][1]);
                acc[1][0] = ffma2(b1, pv.x, acc[1][0]); acc[1][1] = ffma2(b1, pv.y, acc[1][1]);
                acc[2][0] = ffma2(b2, pv.x, acc[2][0]); acc[2][1] = ffma2(b2, pv.y, acc[2][1]);
                acc[3][0] = ffma2(b3, pv.x, acc[3][0]); acc[3][1] = ffma2(b3, pv.y, acc[3][1]);
            }
        }

        // dd values (log2 domain), local max.
        float dd[4][4];
        float mx = -1e30f;
        #pragma unroll
        for (int i = 0; i < 4; i++) {
            float2 lo = unpack2(acc[i][0]);
            float2 hi = unpack2(acc[i][1]);
            dd[i][0] = lo.x; dd[i][1] = lo.y;
            dd[i][2] = hi.x; dd[i][3] = hi.y;
            mx = fmaxf(mx, fmaxf(fmaxf(dd[i][0], dd[i][1]), fmaxf(dd[i][2], dd[i][3])));
        }
        #pragma unroll
        for (int o = 16; o; o >>= 1) mx = fmaxf(mx, __shfl_xor_sync(0xffffffffu, mx, o));
        if (lane == 0) wmax[w] = mx;
        __syncthreads();
        float smax = wmax[0];
        #pragma unroll
        for (int i = 1; i < 8; i++) smax = fmaxf(smax, wmax[i]);

        if (smax > M) {   // CTA-uniform
            float sc = exp2f(M - smax);
            u64 sc2 = pack2(sc, sc);
            #pragma unroll
            for (int i = 0; i < 16; i++) ctx2[i] = fmul2(ctx2[i], sc2);
            ks0 *= sc; ks1 *= sc; ks2 *= sc; ks3 *= sc;
            M = smax;
        }

        // exp2 in regs: group i==0 via FFMA2 poly, i=1..3 via MUFU (pipe split).
        #pragma unroll
        for (int i = 0; i < 4; i++) {
            float dmi = diag_r[i] + M;
            float k0, k1, k2v, k3v;
            if (i == 0) {
                u64 ea = exp2_poly2(dd[i][0] - dmi, dd[i][1] - dmi);
                u64 eb = exp2_poly2(dd[i][2] - dmi, dd[i][3] - dmi);
                float2 fa = unpack2(ea), fb = unpack2(eb);
                k0 = fa.x; k1 = fa.y; k2v = fb.x; k3v = fb.y;
            } else {
                k0  = exp2f(dd[i][0] - dmi);
                k1  = exp2f(dd[i][1] - dmi);
                k2v = exp2f(dd[i][2] - dmi);
                k3v = exp2f(dd[i][3] - dmi);
            }
            ks0 += k0; ks1 += k1; ks2 += k2v; ks3 += k3v;
            *(float4*)(kps + (w * 4 + i) * 132 + lane * 4) = make_float4(k0, k1, k2v, k3v);
        }
        __syncthreads();

        // ctx outer product: features lane*4..+3  x  e-cols w*8..+7.
        #pragma unroll 4
        for (int r = 0; r < 32; r++) {
            ulonglong2 kp4 = *(const ulonglong2*)(kps + r * 132 + lane * 4);
            float2 klo = unpack2(kp4.x), khi = unpack2(kp4.y);
            u64 b0 = pack2(klo.x, klo.x), b1 = pack2(klo.y, klo.y);
            u64 b2 = pack2(khi.x, khi.x), b3 = pack2(khi.y, khi.y);
            const ulonglong2* vp = (const ulonglong2*)(vsb + r * 64 + w * 8);
            ulonglong2 vA = vp[0], vB = vp[1];
            ctx2[0]  = ffma2(b0, vA.x, ctx2[0]);  ctx2[1]  = ffma2(b0, vA.y, ctx2[1]);
            ctx2[2]  = ffma2(b0, vB.x, ctx2[2]);  ctx2[3]  = ffma2(b0, vB.y, ctx2[3]);
            ctx2[4]  = ffma2(b1, vA.x, ctx2[4]);  ctx2[5]  = ffma2(b1, vA.y, ctx2[5]);
            ctx2[6]  = ffma2(b1, vB.x, ctx2[6]);  ctx2[7]  = ffma2(b1, vB.y, ctx2[7]);
            ctx2[8]  = ffma2(b2, vA.x, ctx2[8]);  ctx2[9]  = ffma2(b2, vA.y, ctx2[9]);
            ctx2[10] = ffma2(b2, vB.x, ctx2[10]); ctx2[11] = ffma2(b2, vB.y, ctx2[11]);
            ctx2[12] = ffma2(b3, vA.x, ctx2[12]); ctx2[13] = ffma2(b3, vA.y, ctx2[13]);
            ctx2[14] = ffma2(b3, vB.x, ctx2[14]); ctx2[15] = ffma2(b3, vB.y, ctx2[15]);
        }
    }

    __syncthreads();   // done with kps as kp buffer; reuse for ksum reduce

    // Write ctx partials: feature f = fbase + lane*4 + j, e = w*8..+7.
    {
        float* base = g_ctx_part + ((size_t)(bh * CH + chunk) * MFEAT) * DHEAD;
        #pragma unroll
        for (int j = 0; j < 4; j++) {
            float* op = base + (size_t)(fbase + lane * 4 + j) * DHEAD + w * 8;
            ((ulonglong2*)op)[0] = make_ulonglong2(ctx2[j * 4 + 0], ctx2[j * 4 + 1]);
            ((ulonglong2*)op)[1] = make_ulonglong2(ctx2[j * 4 + 2], ctx2[j * 4 + 3]);
        }
    }

    // ksum: warp partials -> cross-warp reduce through kps area.
    *(float4*)(kps + w * 128 + lane * 4) = make_float4(ks0, ks1, ks2, ks3);
    __syncthreads();
    if (t < 128) {
        float s = 0.f;
        #pragma unroll
        for (int w2 = 0; w2 < 8; w2++) s += kps[w2 * 128 + t];
        g_ksum_part[(bh * CH + chunk) * MFEAT + fbase + t] = s;
    }
    if (t == 0) g_lmax[(bh * CH + chunk) * 2 + fh] = M;
}

// ---------------------------------------------------------------------------
// vsum[bh][e] = sum_n V[bh][n][e]
// ---------------------------------------------------------------------------
__global__ __launch_bounds__(256) void kvsum(const float* __restrict__ V) {
    __shared__ float psum[16][64];
    const int bh = blockIdx.x, t = threadIdx.x;
    const int e4 = t & 15, rc = t >> 4;
    const float4* vb = (const float4*)V + (size_t)bh * NSEQ * 16;
    float4 acc = make_float4(0.f, 0.f, 0.f, 0.f);
    #pragma unroll 8
    for (int it = 0; it < 256; it++) {
        float4 a = vb[(size_t)(rc + 16 * it) * 16 + e4];
        acc.x += a.x; acc.y += a.y; acc.z += a.z; acc.w += a.w;
    }
    psum[rc][e4*4+0] = acc.x; psum[rc][e4*4+1] = acc.y;
    psum[rc][e4*4+2] = acc.z; psum[rc][e4*4+3] = acc.w;
    __syncthreads();
    if (t < 64) {
        float s = 0.f;
        #pragma unroll
        for (int r = 0; r < 16; r++) s += psum[r][t];
        g_vsum[bh * 64 + t] = s;
    }
}

// ---------------------------------------------------------------------------
// Per-bh global stab + per-(chunk,fh) scale factors (log2 domain).
// ---------------------------------------------------------------------------
__global__ void kscale() {
    const int bh = threadIdx.x;  // 64 threads
    float mx = -1e30f;
    #pragma unroll
    for (int c = 0; c < CH * 2; c++) mx = fmaxf(mx, g_lmax[bh * CH * 2 + c]);
    #pragma unroll
    for (int c = 0; c < CH * 2; c++)
        g_scale[bh * CH * 2 + c] = exp2f(g_lmax[bh * CH * 2 + c] - mx);
}

// ---------------------------------------------------------------------------
// Reduce partials with rescale; add eps terms; apply RATIO.
// ---------------------------------------------------------------------------
__global__ void k2_reduce() {
    const size_t NCTX = (size_t)BH * MFEAT * DHEAD;  // 1048576
    size_t idx = (size_t)blockIdx.x * 256 + threadIdx.x;
    if (idx < NCTX) {
        size_t bh = idx >> 14;
        size_t rem = idx & 16383;
        size_t feat = rem >> 6;
        size_t fh = feat >> 7;
        size_t e = idx & 63;
        float s = 0.f;
        #pragma unroll
        for (int c = 0; c < CH; c++)
            s += g_scale[bh * CH * 2 + c * 2 + fh] *
                 g_ctx_part[(((size_t)bh * CH + c) << 14) + rem];
        g_ctx[idx] = RATIO * (s + KEPS * g_vsum[(bh << 6) + e]);
    } else if (idx < NCTX + (size_t)BH * MFEAT) {
        size_t i2 = idx - NCTX;
        size_t bh = i2 >> 8, j = i2 & 255;
        size_t fh = j >> 7;
        float s = 0.f;
        #pragma unroll
        for (int c = 0; c < CH; c++)
            s += g_scale[bh * CH * 2 + c * 2 + fh] *
                 g_ksum_part[(bh * CH + c) * MFEAT + j];
        g_ksum[i2] = RATIO * (s + KEPS * (float)NSEQ);
    }
}

// ---------------------------------------------------------------------------
// k3: q features + D_inv + output GEMM. 64-row tiles, 2 CTAs/SM.
// ctx staged through shared (cp.async double buffer). exp2 in log2 domain,
// split MUFU / FFMA2-poly.
// ---------------------------------------------------------------------------
#define K3_SMEM_BYTES (66560 + 32768)

__global__ __launch_bounds__(256, 2) void k3_out(const float* __restrict__ Q,
                                                 const float* __restrict__ P,
                                                 float* __restrict__ O) {
    extern __shared__ __align__(16) char smraw[];
    float (*dds)[260] = (float (*)[260])smraw;            // [64][260]
    float* ovl  = (float*)(smraw + 66560);
    float (*qsm)[64] = (float (*)[64])ovl;                // phase 1 only
    float* ctxs = ovl;                                    // phase 2: 2 x 4096 floats
    __shared__ float ksum_s[256];
    __shared__ float diag[64];
    __shared__ float rmax[64];
    __shared__ float dinv[64];

    const int bh = blockIdx.y, tile = blockIdx.x, t = threadIdx.x;
    const int w = t >> 5, lane = t & 31;

    u64 p2[32];
    {
        const ulonglong2* pr = (const ulonglong2*)(P + t * 64);
        const u64 dnl2 = pack2(DN_L2E, DN_L2E);
        #pragma unroll
        for (int i = 0; i < 16; i++) {
            ulonglong2 tt = pr[i];
            p2[2*i]   = fmul2(tt.x, dnl2);
            p2[2*i+1] = fmul2(tt.y, dnl2);
        }
    }
    ksum_s[t] = g_ksum[bh * MFEAT + t];

    // Load Q tile (64 x 64) + per-row diag (log2 domain) via 16-lane shuffles.
    {
        const float4* qb = (const float4*)(Q + ((size_t)bh * NSEQ + (size_t)tile * 64) * DHEAD);
        float4* qs = (float4*)&qsm[0][0];
        #pragma unroll
        for (int kq = 0; kq < 4; kq++) {
            int i = t + 256 * kq;          // float4 index; row = i >> 4
            float4 a = qb[i];
            qs[i] = a;
            float ss = a.x*a.x + a.y*a.y + a.z*a.z + a.w*a.w;
            #pragma unroll
            for (int o = 1; o < 16; o <<= 1) ss += __shfl_xor_sync(0xffffffffu, ss, o);
            if ((t & 15) == 0) diag[i >> 4] = HDN2_L2E * ss;
        }
    }
    __syncthreads();

    // dd[r][t] = dot(q[r], scaled_proj[t])  (log2 domain)
    #pragma unroll 2
    for (int r = 0; r < 64; r++) {
        const ulonglong2* qrow = (const ulonglong2*)qsm[r];
        u64 acc0 = 0, acc1 = 0, acc2 = 0, acc3 = 0;
        #pragma unroll
        for (int i = 0; i < 8; i++) {
            ulonglong2 qa = qrow[2*i];
            ulonglong2 qb2 = qrow[2*i+1];
            acc0 = ffma2(qa.x,  p2[4*i],   acc0);
            acc1 = ffma2(qa.y,  p2[4*i+1], acc1);
            acc2 = ffma2(qb2.x, p2[4*i+2], acc2);
            acc3 = ffma2(qb2.y, p2[4*i+3], acc3);
        }
        float2 f0 = unpack2(acc0), f1 = unpack2(acc1);
        float2 f2 = unpack2(acc2), f3 = unpack2(acc3);
        dds[r][t] = ((f0.x + f0.y) + (f1.x + f1.y)) + ((f2.x + f2.y) + (f3.x + f3.y));
    }
    __syncthreads();   // qsm dead after this point

    // Prologue: stage ctx chunk 0 (features 0..63) into buf 0.
    const uint32_t ctx_s = (uint32_t)__cvta_generic_to_shared(ctxs);
    const float* cgb = g_ctx + (size_t)bh * MFEAT * DHEAD;
    {
        #pragma unroll
        for (int q = 0; q < 4; q++) {
            int i = t + 256 * q;                 // float4 index in 16KB chunk
            cp_async16(ctx_s + i * 16, cgb + i * 4);
        }
        cp_commit();
    }

    // Per-row max (8 rows per warp).
    #pragma unroll
    for (int rr = 0; rr < 8; rr++) {
        int r = w * 8 + rr;
        float m = dds[r][lane];
        #pragma unroll
        for (int c = 1; c < 8; c++) m = fmaxf(m, dds[r][lane + 32 * c]);
        #pragma unroll
        for (int o = 16; o; o >>= 1) m = fmaxf(m, __shfl_xor_sync(0xffffffffu, m, o));
        if (lane == 0) rmax[r] = m;
    }
    __syncthreads();

    // q' in place: exp2 split between MUFU and FFMA2 poly (~1/3 poly).
    #pragma unroll
    for (int pr = 0; pr < 32; pr++) {
        int r = pr * 2;
        float y0 = dds[r][t]     - (diag[r]     + rmax[r]);
        float y1 = dds[r + 1][t] - (diag[r + 1] + rmax[r + 1]);
        float k0, k1;
        if (pr % 3 == 0) {
            float2 ee = unpack2(exp2_poly2(y0, y1));
            k0 = ee.x; k1 = ee.y;
        } else {
            k0 = exp2f(y0); k1 = exp2f(y1);
        }
        dds[r][t]     = RATIO * (k0 + KEPS);
        dds[r + 1][t] = RATIO * (k1 + KEPS);
    }
    __syncthreads();

    // D_inv (8 rows per warp).
    #pragma unroll
    for (int rr = 0; rr < 8; rr++) {
        int r = w * 8 + rr;
        float s = 0.f;
        #pragma unroll
        for (int c = 0; c < 8; c++)
            s = fmaf(dds[r][lane + 32 * c], ksum_s[lane + 32 * c], s);
        #pragma unroll
        for (int o = 16; o; o >>= 1) s += __shfl_xor_sync(0xffffffffu, s, o);
        if (lane == 0) dinv[r] = 1.0f / s;
    }

    // out: 2 rows x 8 cols per thread; ctx from shared, chunked 4 x 64 features.
    const int rs = t >> 3;            // rows rs, rs+32
    const int ecg = (t & 7) * 2;      // ulonglong2 index within 64-float row
    u64 a0[4], a1[4];
    #pragma unroll
    for (int i = 0; i < 4; i++) { a0[i] = 0ull; a1[i] = 0ull; }

    #pragma unroll
    for (int c = 0; c < 4; c++) {
        if (c + 1 < 4) {
            uint32_t dst = ctx_s + ((c + 1) & 1) * 16384;
            const float* src = cgb + (c + 1) * 4096;
            #pragma unroll
            for (int q = 0; q < 4; q++) {
                int i = t + 256 * q;
                cp_async16(dst + i * 16, src + i * 4);
            }
            cp_commit();
            cp_wait<1>();
        } else {
            cp_wait<0>();
        }
        __syncthreads();   // chunk c visible; also orders reuse of buffers

        const ulonglong2* cc = (const ulonglong2*)(ctxs + (c & 1) * 4096);
        #pragma unroll 4
        for (int jl = 0; jl < 64; jl++) {
            int jj = c * 64 + jl;
            ulonglong2 cA = cc[jl * 16 + ecg];
            ulonglong2 cB = cc[jl * 16 + ecg + 1];
            float v0 = dds[rs][jj];
            float v1 = dds[rs + 32][jj];
            u64 q0 = pack2(v0, v0), q1 = pack2(v1, v1);
            a0[0] = ffma2(q0, cA.x, a0[0]); a0[1] = ffma2(q0, cA.y, a0[1]);
            a0[2] = ffma2(q0, cB.x, a0[2]); a0[3] = ffma2(q0, cB.y, a0[3]);
            a1[0] = ffma2(q1, cA.x, a1[0]); a1[1] = ffma2(q1, cA.y, a1[1]);
            a1[2] = ffma2(q1, cB.x, a1[2]); a1[3] = ffma2(q1, cB.y, a1[3]);
        }
        __syncthreads();   // all warps done with buf (c&1) before it is refilled
    }

    const size_t rowbase = (size_t)bh * NSEQ + (size_t)tile * 64;
    {
        u64 d2 = pack2(dinv[rs], dinv[rs]);
        float* ob = O + (rowbase + rs) * DHEAD + (size_t)ecg * 4;
        ((ulonglong2*)ob)[0] = make_ulonglong2(fmul2(a0[0], d2), fmul2(a0[1], d2));
        ((ulonglong2*)ob)[1] = make_ulonglong2(fmul2(a0[2], d2), fmul2(a0[3], d2));
        d2 = pack2(dinv[rs + 32], dinv[rs + 32]);
        ob = O + (rowbase + rs + 32) * DHEAD + (size_t)ecg * 4;
        ((ulonglong2*)ob)[0] = make_ulonglong2(fmul2(a1[0], d2), fmul2(a1[1], d2));
        ((ulonglong2*)ob)[1] = make_ulonglong2(fmul2(a1[2], d2), fmul2(a1[3], d2));
    }
}

// ---------------------------------------------------------------------------
extern "C" void kernel_launch(void* const* d_in, const int* in_sizes, int n_in,
                              void* d_out, int out_size) {
    const float* q    = (const float*)d_in[0];
    const float* k    = (const float*)d_in[1];
    const float* v    = (const float*)d_in[2];
    const float* proj = (const float*)d_in[3];
    float* out = (float*)d_out;

    cudaFuncSetAttribute(k12_ctx, cudaFuncAttributeMaxDynamicSharedMemorySize, K12_SMEM);
    cudaFuncSetAttribute(k3_out, cudaFuncAttributeMaxDynamicSharedMemorySize, K3_SMEM_BYTES);

    k12_ctx<<<dim3(CH * 2, BH), 256, K12_SMEM>>>(k, v, proj);
    kvsum<<<BH, 256>>>(v);
    kscale<<<1, BH>>>();
    {
        const size_t total = (size_t)BH * MFEAT * DHEAD + (size_t)BH * MFEAT;
        k2_reduce<<<(unsigned)((total + 255) / 256), 256>>>();
    }
    k3_out<<<dim3(NSEQ / 64, BH), 256, K3_SMEM_BYTES>>>(q, proj, out);
}